// round 2
// baseline (speedup 1.0000x reference)
#include <cuda_runtime.h>
#include <math.h>

#define BB 32
#define TT 4096
#define DD 256
#define HH 128
#define BT (BB*TT)

// ---- scratch (device globals; no allocation) ----
__device__ float g_scores[BT];           // scores, normalized to weights in place
__device__ float g_part[16*BB*DD];       // main_topic partial sums
__device__ float g_tenc[BB*HH];          // normalized topic encoding
__device__ unsigned char g_mask[BT];     // irrelevance mask per (b, freq)

__device__ __forceinline__ float gelu_exact(float v) {
    return 0.5f * v * (1.0f + erff(v * 0.70710678118654752f));
}

// ================= K1: scores[b,t] = dot(q, x[b,t]) / TEMP =================
__global__ void __launch_bounds__(256) k_scores(const float* __restrict__ x,
                                                const float* __restrict__ tq) {
    int warp = (blockIdx.x * blockDim.x + threadIdx.x) >> 5;
    int lane = threadIdx.x & 31;
    if (warp >= BT) return;
    const float* xr = x + (size_t)warp * DD;
    float s = 0.f;
#pragma unroll
    for (int i = 0; i < 8; i++) {
        int c = lane + 32 * i;
        s += xr[c] * __ldg(tq + c);
    }
#pragma unroll
    for (int o = 16; o; o >>= 1) s += __shfl_xor_sync(0xffffffffu, s, o);
    if (lane == 0) g_scores[warp] = s * 2.0f;   // 1/TEMPERATURE = 2
}

// ================= K2: per-b softmax over T, in place =================
__global__ void __launch_bounds__(256) k_softmax() {
    int b = blockIdx.x;
    int tid = threadIdx.x;
    __shared__ float red[256];
    float* s = g_scores + b * TT;
    float v[16];
    float mx = -1e30f;
#pragma unroll
    for (int i = 0; i < 16; i++) { v[i] = s[tid + 256 * i]; mx = fmaxf(mx, v[i]); }
    red[tid] = mx; __syncthreads();
    for (int o = 128; o; o >>= 1) { if (tid < o) red[tid] = fmaxf(red[tid], red[tid + o]); __syncthreads(); }
    mx = red[0]; __syncthreads();
    float sum = 0.f;
#pragma unroll
    for (int i = 0; i < 16; i++) { v[i] = expf(v[i] - mx); sum += v[i]; }
    red[tid] = sum; __syncthreads();
    for (int o = 128; o; o >>= 1) { if (tid < o) red[tid] += red[tid + o]; __syncthreads(); }
    float inv = 1.0f / red[0];
#pragma unroll
    for (int i = 0; i < 16; i++) s[tid + 256 * i] = v[i] * inv;
}

// ================= K3: main_topic partials over t-chunks =================
__global__ void __launch_bounds__(256) k_topic_part(const float* __restrict__ x) {
    int chunk = blockIdx.x;          // 0..15
    int b = blockIdx.y;              // 0..31
    int d = threadIdx.x;             // 0..255
    __shared__ float w[256];
    int t0 = chunk * 256;
    w[d] = g_scores[b * TT + t0 + d];
    __syncthreads();
    float acc = 0.f;
    const float* xp = x + ((size_t)b * TT + t0) * DD + d;
#pragma unroll 4
    for (int t = 0; t < 256; t++) acc += w[t] * xp[(size_t)t * DD];
    g_part[(chunk * BB + b) * DD + d] = acc;
}

// ================= K4: encode main_topic, normalize =================
__global__ void __launch_bounds__(256) k_topic_enc(
    const float* __restrict__ W1, const float* __restrict__ b1,
    const float* __restrict__ lng, const float* __restrict__ lnb,
    const float* __restrict__ W2, const float* __restrict__ b2) {
    int b = blockIdx.x, tid = threadIdx.x;
    __shared__ float mt[256], red[256], red2[256], gbuf[256];
    float acc = 0.f;
#pragma unroll
    for (int c = 0; c < 16; c++) acc += g_part[(c * BB + b) * DD + tid];
    mt[tid] = acc;
    __syncthreads();
    float h = b1[tid];
    for (int k = 0; k < DD; k++) h += mt[k] * W1[k * DD + tid];
    red[tid] = h; red2[tid] = h * h;
    __syncthreads();
    for (int o = 128; o; o >>= 1) {
        if (tid < o) { red[tid] += red[tid + o]; red2[tid] += red2[tid + o]; }
        __syncthreads();
    }
    float mu = red[0] * (1.f / 256.f);
    float var = red2[0] * (1.f / 256.f) - mu * mu;
    float n = (h - mu) * rsqrtf(var + 1e-5f) * lng[tid] + lnb[tid];
    float g = gelu_exact(n);
    __syncthreads();
    gbuf[tid] = g;
    __syncthreads();
    float e = 0.f;
    if (tid < HH) {
        e = b2[tid];
        for (int k = 0; k < DD; k++) e += gbuf[k] * W2[k * HH + tid];
    }
    red[tid] = (tid < HH) ? e * e : 0.f;
    __syncthreads();
    for (int o = 128; o; o >>= 1) { if (tid < o) red[tid] += red[tid + o]; __syncthreads(); }
    if (tid < HH) {
        float nrm = fmaxf(sqrtf(red[0]), 1e-12f);
        g_tenc[b * HH + tid] = e / nrm;
    }
}

// ================= K5: encoder GEMMs + LN + GELU + relevance mask =================
// 64 rows per CTA, 256 threads, 8x8 reg tile GEMM1, 8x4 reg tile GEMM2.
__global__ void __launch_bounds__(256) k_encode_mask(
    const float* __restrict__ x, const float* __restrict__ W1,
    const float* __restrict__ b1, const float* __restrict__ lng,
    const float* __restrict__ lnb, const float* __restrict__ W2,
    const float* __restrict__ b2) {
    extern __shared__ float sm[];
    float* As = sm;                  // [16][65]  (phase A)
    float* Bs = sm + 16 * 65;        // [16][256] (phase A)
    float* G   = sm;                 // [64][256] (phase B, aliases)
    float* W2s = sm + 64 * 256;      // [32][128] (phase B)

    int tid = threadIdx.x;
    int tx = tid & 31, ty = tid >> 5;        // 32 x 8
    int row0 = blockIdx.x * 64;
    int b = row0 >> 12;                       // T = 4096

    float acc[8][8];
#pragma unroll
    for (int i = 0; i < 8; i++)
#pragma unroll
        for (int j = 0; j < 8; j++) acc[i][j] = 0.f;

    for (int kb = 0; kb < 16; kb++) {
        int k0 = kb * 16;
        __syncthreads();
#pragma unroll
        for (int it = 0; it < 4; it++) {
            int lin = it * 256 + tid;
            int r = lin >> 4, kk = lin & 15;
            As[kk * 65 + r] = x[((size_t)(row0 + r)) * DD + k0 + kk];
        }
#pragma unroll
        for (int it = 0; it < 16; it++)
            Bs[it * 256 + tid] = W1[(size_t)(k0 + it) * DD + tid];
        __syncthreads();
#pragma unroll
        for (int kk = 0; kk < 16; kk++) {
            float a[8], bb[8];
#pragma unroll
            for (int i = 0; i < 8; i++) a[i] = As[kk * 65 + ty * 8 + i];
#pragma unroll
            for (int j = 0; j < 8; j++) bb[j] = Bs[kk * 256 + tx + 32 * j];
#pragma unroll
            for (int i = 0; i < 8; i++)
#pragma unroll
                for (int j = 0; j < 8; j++) acc[i][j] += a[i] * bb[j];
        }
    }

    // epilogue 1: +b1, LayerNorm per row (warp owns 8 rows), GELU -> G smem
    float bv[8], gv[8], btv[8];
#pragma unroll
    for (int j = 0; j < 8; j++) {
        int c = tx + 32 * j;
        bv[j] = b1[c]; gv[j] = lng[c]; btv[j] = lnb[c];
    }
    __syncthreads();   // done with As/Bs before overwriting with G
#pragma unroll
    for (int i = 0; i < 8; i++) {
        float s = 0.f, s2 = 0.f;
#pragma unroll
        for (int j = 0; j < 8; j++) {
            float h = acc[i][j] + bv[j];
            acc[i][j] = h; s += h; s2 += h * h;
        }
#pragma unroll
        for (int o = 16; o; o >>= 1) {
            s  += __shfl_xor_sync(0xffffffffu, s, o);
            s2 += __shfl_xor_sync(0xffffffffu, s2, o);
        }
        float mu = s * (1.f / 256.f);
        float var = s2 * (1.f / 256.f) - mu * mu;
        float rstd = rsqrtf(var + 1e-5f);
        int r = ty * 8 + i;
#pragma unroll
        for (int j = 0; j < 8; j++) {
            float nrm = (acc[i][j] - mu) * rstd * gv[j] + btv[j];
            G[r * 256 + tx + 32 * j] = gelu_exact(nrm);
        }
    }
    __syncthreads();

    // phase B: GEMM2 [64,256] x [256,128]
    float acc2[8][4];
#pragma unroll
    for (int i = 0; i < 8; i++)
#pragma unroll
        for (int j = 0; j < 4; j++) acc2[i][j] = 0.f;
    for (int kb = 0; kb < 8; kb++) {
#pragma unroll
        for (int it = 0; it < 16; it++) {
            int lin = it * 256 + tid;
            int kk = lin >> 7, c = lin & 127;
            W2s[kk * 128 + c] = W2[(size_t)(kb * 32 + kk) * HH + c];
        }
        __syncthreads();
#pragma unroll
        for (int kk = 0; kk < 32; kk++) {
            float a[8], bb[4];
#pragma unroll
            for (int i = 0; i < 8; i++) a[i] = G[(ty * 8 + i) * 256 + kb * 32 + kk];
#pragma unroll
            for (int j = 0; j < 4; j++) bb[j] = W2s[kk * 128 + tx + 32 * j];
#pragma unroll
            for (int i = 0; i < 8; i++)
#pragma unroll
                for (int j = 0; j < 4; j++) acc2[i][j] += a[i] * bb[j];
        }
        __syncthreads();
    }

    // epilogue 2: +b2, cosine relevance vs normalized topic encoding, mask
    float tqv[4], b2v[4];
#pragma unroll
    for (int j = 0; j < 4; j++) {
        int c = tx + 32 * j;
        tqv[j] = g_tenc[b * HH + c];
        b2v[j] = b2[c];
    }
#pragma unroll
    for (int i = 0; i < 8; i++) {
        float ss = 0.f, dt = 0.f;
#pragma unroll
        for (int j = 0; j < 4; j++) {
            float e = acc2[i][j] + b2v[j];
            ss += e * e; dt += e * tqv[j];
        }
#pragma unroll
        for (int o = 16; o; o >>= 1) {
            ss += __shfl_xor_sync(0xffffffffu, ss, o);
            dt += __shfl_xor_sync(0xffffffffu, dt, o);
        }
        float rel = dt / fmaxf(sqrtf(ss), 1e-12f);
        if (tx == i) g_mask[row0 + ty * 8 + i] = (rel < 0.4f) ? 1 : 0;
    }
}

// ================= K6: fused FFT -> mask multiply -> IFFT per (b,d) channel ====
// out = x + Re(c_q * ifft(mask .* fft(x))),  c_q = exp(i*sf[q]) - 1
// Radix-4: forward DIF (natural -> base4-digit-reversed), multiply in permuted
// order, mirrored inverse (digit-reversed -> natural). No bit-reversal pass.
__global__ void __launch_bounds__(256) k_fft_filter(
    const float* __restrict__ x, const float* __restrict__ sf,
    float* __restrict__ out) {
    __shared__ float twr[1024], twi[1024];
    __shared__ float re[4096], im[4096];
    int tid = threadIdx.x;
    int bd = blockIdx.x;
    int b = bd >> 8;
    int d = bd & 255;

    for (int j = tid; j < 1024; j += 256) {
        float sv, cv;
        sincospif(j * (2.0f / 4096.0f), &sv, &cv);
        twr[j] = cv; twi[j] = -sv;          // e^{-2*pi*i*j/4096}
    }

    float xreg[16];
    const float* xp = x + (size_t)b * TT * DD + d;
#pragma unroll
    for (int i = 0; i < 16; i++) {
        int t = tid + 256 * i;
        float v = xp[(size_t)t * DD];
        xreg[i] = v;
        re[t] = v; im[t] = 0.f;
    }
    __syncthreads();

    // ---- forward radix-4 DIF ----
#pragma unroll
    for (int len = 1024; len >= 1; len >>= 2) {
        int step = 1024 / len;
#pragma unroll
        for (int u = 0; u < 4; u++) {
            int k = tid + 256 * u;
            int pos = k & (len - 1);
            int i0 = ((k - pos) << 2) + pos;
            float a0r = re[i0],            a0i = im[i0];
            float a1r = re[i0 + len],      a1i = im[i0 + len];
            float a2r = re[i0 + 2 * len],  a2i = im[i0 + 2 * len];
            float a3r = re[i0 + 3 * len],  a3i = im[i0 + 3 * len];
            float s02r = a0r + a2r, s02i = a0i + a2i;
            float d02r = a0r - a2r, d02i = a0i - a2i;
            float s13r = a1r + a3r, s13i = a1i + a3i;
            float d13r = a1r - a3r, d13i = a1i - a3i;
            float y0r = s02r + s13r, y0i = s02i + s13i;
            float y1r = d02r + d13i, y1i = d02i - d13r;   // d02 - j*d13
            float y2r = s02r - s13r, y2i = s02i - s13i;
            float y3r = d02r - d13i, y3i = d02i + d13r;   // d02 + j*d13
            int e = pos * step;
            float w1r = twr[e], w1i = twi[e];
            float w2r = w1r * w1r - w1i * w1i, w2i = 2.f * w1r * w1i;
            float w3r = w1r * w2r - w1i * w2i, w3i = w1r * w2i + w1i * w2r;
            re[i0] = y0r;                               im[i0] = y0i;
            re[i0 + len]     = y1r * w1r - y1i * w1i;   im[i0 + len]     = y1r * w1i + y1i * w1r;
            re[i0 + 2 * len] = y2r * w2r - y2i * w2i;   im[i0 + 2 * len] = y2r * w2i + y2i * w2r;
            re[i0 + 3 * len] = y3r * w3r - y3i * w3i;   im[i0 + 3 * len] = y3r * w3i + y3i * w3r;
        }
        __syncthreads();
    }

    // ---- mask multiply (element p holds X[digitrev4(p)]) ----
    const unsigned char* mk = g_mask + b * TT;
#pragma unroll
    for (int i = 0; i < 16; i++) {
        int p = tid + 256 * i;
        int f = 0, pp = p;
#pragma unroll
        for (int s = 0; s < 6; s++) { f = (f << 2) | (pp & 3); pp >>= 2; }
        if (!mk[f]) { re[p] = 0.f; im[p] = 0.f; }
    }
    __syncthreads();

    // ---- inverse: mirror stages, conjugate twiddles (unnormalized, x N) ----
#pragma unroll
    for (int len = 1; len <= 1024; len <<= 2) {
        int step = 1024 / len;
#pragma unroll
        for (int u = 0; u < 4; u++) {
            int k = tid + 256 * u;
            int pos = k & (len - 1);
            int i0 = ((k - pos) << 2) + pos;
            float y0r = re[i0],           y0i = im[i0];
            float y1r = re[i0 + len],     y1i = im[i0 + len];
            float y2r = re[i0 + 2 * len], y2i = im[i0 + 2 * len];
            float y3r = re[i0 + 3 * len], y3i = im[i0 + 3 * len];
            int e = pos * step;
            float w1r = twr[e], w1i = -twi[e];
            float w2r = w1r * w1r - w1i * w1i, w2i = 2.f * w1r * w1i;
            float w3r = w1r * w2r - w1i * w2i, w3i = w1r * w2i + w1i * w2r;
            float z1r = y1r * w1r - y1i * w1i, z1i = y1r * w1i + y1i * w1r;
            float z2r = y2r * w2r - y2i * w2i, z2i = y2r * w2i + y2i * w2r;
            float z3r = y3r * w3r - y3i * w3i, z3i = y3r * w3i + y3i * w3r;
            float s02r = y0r + z2r, s02i = y0i + z2i;
            float d02r = y0r - z2r, d02i = y0i - z2i;
            float s13r = z1r + z3r, s13i = z1i + z3i;
            float d13r = z1r - z3r, d13i = z1i - z3i;
            re[i0]           = s02r + s13r;  im[i0]           = s02i + s13i;
            re[i0 + len]     = d02r - d13i;  im[i0 + len]     = d02i + d13r;  // d02 + j*d13
            re[i0 + 2 * len] = s02r - s13r;  im[i0 + 2 * len] = s02i - s13i;
            re[i0 + 3 * len] = d02r + d13i;  im[i0 + 3 * len] = d02i - d13r;  // d02 - j*d13
        }
        __syncthreads();
    }

    // ---- combine: out = x + Re(c) * Re(u)/N - Im(c) * Im(u)/N ----
    float q = sf[d & 3];
    float cr = (cosf(q) - 1.0f) * (1.0f / 4096.0f);
    float ci = sinf(q) * (1.0f / 4096.0f);
    float* op = out + (size_t)b * TT * DD + d;
#pragma unroll
    for (int i = 0; i < 16; i++) {
        int t = tid + 256 * i;
        op[(size_t)t * DD] = xreg[i] + cr * re[t] - ci * im[t];
    }
}

// ================= launch =================
extern "C" void kernel_launch(void* const* d_in, const int* in_sizes, int n_in,
                              void* d_out, int out_size) {
    const float* x    = (const float*)d_in[0];
    const float* W1   = (const float*)d_in[1];
    const float* b1   = (const float*)d_in[2];
    const float* ln_g = (const float*)d_in[3];
    const float* ln_b = (const float*)d_in[4];
    const float* W2   = (const float*)d_in[5];
    const float* b2   = (const float*)d_in[6];
    const float* tq   = (const float*)d_in[7];
    const float* sf   = (const float*)d_in[8];
    float* out = (float*)d_out;

    cudaFuncSetAttribute(k_encode_mask, cudaFuncAttributeMaxDynamicSharedMemorySize, 81920);

    k_scores<<<BT / 8, 256>>>(x, tq);
    k_softmax<<<BB, 256>>>();
    k_topic_part<<<dim3(16, BB), 256>>>(x);
    k_topic_enc<<<BB, 256>>>(W1, b1, ln_g, ln_b, W2, b2);
    k_encode_mask<<<BT / 64, 256, 81920>>>(x, W1, b1, ln_g, ln_b, W2, b2);
    k_fft_filter<<<BB * DD, 256>>>(x, sf, out);
}

// round 6
// speedup vs baseline: 1.0015x; 1.0015x over previous
#include <cuda_runtime.h>
#include <math.h>

#define BB 32
#define TT 4096
#define DD 256
#define HH 128
#define BT (BB*TT)

// ---- scratch (device globals; no allocation) ----
__device__ float g_scores[BT];           // scores, normalized to weights in place
__device__ float g_part[16*BB*DD];       // main_topic partial sums
__device__ float g_tenc[BB*HH];          // normalized topic encoding
__device__ unsigned char g_mask[BT];     // irrelevance mask per (b, freq)

__device__ __forceinline__ float gelu_exact(float v) {
    return 0.5f * v * (1.0f + erff(v * 0.70710678118654752f));
}

// ================= K1: scores[b,t] = dot(q, x[b,t]) / TEMP =================
__global__ void __launch_bounds__(256) k_scores(const float* __restrict__ x,
                                                const float* __restrict__ tq) {
    int warp = (blockIdx.x * blockDim.x + threadIdx.x) >> 5;
    int lane = threadIdx.x & 31;
    if (warp >= BT) return;
    const float* xr = x + (size_t)warp * DD;
    float s = 0.f;
#pragma unroll
    for (int i = 0; i < 8; i++) {
        int c = lane + 32 * i;
        s += xr[c] * __ldg(tq + c);
    }
#pragma unroll
    for (int o = 16; o; o >>= 1) s += __shfl_xor_sync(0xffffffffu, s, o);
    if (lane == 0) g_scores[warp] = s * 2.0f;   // 1/TEMPERATURE = 2
}

// ================= K2: per-b softmax over T, in place =================
__global__ void __launch_bounds__(256) k_softmax() {
    int b = blockIdx.x;
    int tid = threadIdx.x;
    __shared__ float red[256];
    float* s = g_scores + b * TT;
    float v[16];
    float mx = -1e30f;
#pragma unroll
    for (int i = 0; i < 16; i++) { v[i] = s[tid + 256 * i]; mx = fmaxf(mx, v[i]); }
    red[tid] = mx; __syncthreads();
    for (int o = 128; o; o >>= 1) { if (tid < o) red[tid] = fmaxf(red[tid], red[tid + o]); __syncthreads(); }
    mx = red[0]; __syncthreads();
    float sum = 0.f;
#pragma unroll
    for (int i = 0; i < 16; i++) { v[i] = expf(v[i] - mx); sum += v[i]; }
    red[tid] = sum; __syncthreads();
    for (int o = 128; o; o >>= 1) { if (tid < o) red[tid] += red[tid + o]; __syncthreads(); }
    float inv = 1.0f / red[0];
#pragma unroll
    for (int i = 0; i < 16; i++) s[tid + 256 * i] = v[i] * inv;
}

// ================= K3: main_topic partials over t-chunks =================
__global__ void __launch_bounds__(256) k_topic_part(const float* __restrict__ x) {
    int chunk = blockIdx.x;          // 0..15
    int b = blockIdx.y;              // 0..31
    int d = threadIdx.x;             // 0..255
    __shared__ float w[256];
    int t0 = chunk * 256;
    w[d] = g_scores[b * TT + t0 + d];
    __syncthreads();
    float acc = 0.f;
    const float* xp = x + ((size_t)b * TT + t0) * DD + d;
#pragma unroll 4
    for (int t = 0; t < 256; t++) acc += w[t] * xp[(size_t)t * DD];
    g_part[(chunk * BB + b) * DD + d] = acc;
}

// ================= K4: encode main_topic, normalize =================
__global__ void __launch_bounds__(256) k_topic_enc(
    const float* __restrict__ W1, const float* __restrict__ b1,
    const float* __restrict__ lng, const float* __restrict__ lnb,
    const float* __restrict__ W2, const float* __restrict__ b2) {
    int b = blockIdx.x, tid = threadIdx.x;
    __shared__ float mt[256], red[256], red2[256], gbuf[256];
    float acc = 0.f;
#pragma unroll
    for (int c = 0; c < 16; c++) acc += g_part[(c * BB + b) * DD + tid];
    mt[tid] = acc;
    __syncthreads();
    float h = b1[tid];
    for (int k = 0; k < DD; k++) h += mt[k] * W1[k * DD + tid];
    red[tid] = h; red2[tid] = h * h;
    __syncthreads();
    for (int o = 128; o; o >>= 1) {
        if (tid < o) { red[tid] += red[tid + o]; red2[tid] += red2[tid + o]; }
        __syncthreads();
    }
    float mu = red[0] * (1.f / 256.f);
    float var = red2[0] * (1.f / 256.f) - mu * mu;
    float n = (h - mu) * rsqrtf(var + 1e-5f) * lng[tid] + lnb[tid];
    float g = gelu_exact(n);
    __syncthreads();
    gbuf[tid] = g;
    __syncthreads();
    float e = 0.f;
    if (tid < HH) {
        e = b2[tid];
        for (int k = 0; k < DD; k++) e += gbuf[k] * W2[k * HH + tid];
    }
    red[tid] = (tid < HH) ? e * e : 0.f;
    __syncthreads();
    for (int o = 128; o; o >>= 1) { if (tid < o) red[tid] += red[tid + o]; __syncthreads(); }
    if (tid < HH) {
        float nrm = fmaxf(sqrtf(red[0]), 1e-12f);
        g_tenc[b * HH + tid] = e / nrm;
    }
}

// ================= K5: encoder GEMMs + LN + GELU + relevance mask =================
// 64 rows per CTA, 256 threads, 8x8 reg tile GEMM1, 8x4 reg tile GEMM2.
__global__ void __launch_bounds__(256) k_encode_mask(
    const float* __restrict__ x, const float* __restrict__ W1,
    const float* __restrict__ b1, const float* __restrict__ lng,
    const float* __restrict__ lnb, const float* __restrict__ W2,
    const float* __restrict__ b2) {
    extern __shared__ float sm[];
    float* As = sm;                  // [16][65]  (phase A)
    float* Bs = sm + 16 * 65;        // [16][256] (phase A)
    float* G   = sm;                 // [64][256] (phase B, aliases)
    float* W2s = sm + 64 * 256;      // [32][128] (phase B)

    int tid = threadIdx.x;
    int tx = tid & 31, ty = tid >> 5;        // 32 x 8
    int row0 = blockIdx.x * 64;
    int b = row0 >> 12;                       // T = 4096

    float acc[8][8];
#pragma unroll
    for (int i = 0; i < 8; i++)
#pragma unroll
        for (int j = 0; j < 8; j++) acc[i][j] = 0.f;

    for (int kb = 0; kb < 16; kb++) {
        int k0 = kb * 16;
        __syncthreads();
#pragma unroll
        for (int it = 0; it < 4; it++) {
            int lin = it * 256 + tid;
            int r = lin >> 4, kk = lin & 15;
            As[kk * 65 + r] = x[((size_t)(row0 + r)) * DD + k0 + kk];
        }
#pragma unroll
        for (int it = 0; it < 16; it++)
            Bs[it * 256 + tid] = W1[(size_t)(k0 + it) * DD + tid];
        __syncthreads();
#pragma unroll
        for (int kk = 0; kk < 16; kk++) {
            float a[8], bb[8];
#pragma unroll
            for (int i = 0; i < 8; i++) a[i] = As[kk * 65 + ty * 8 + i];
#pragma unroll
            for (int j = 0; j < 8; j++) bb[j] = Bs[kk * 256 + tx + 32 * j];
#pragma unroll
            for (int i = 0; i < 8; i++)
#pragma unroll
                for (int j = 0; j < 8; j++) acc[i][j] += a[i] * bb[j];
        }
    }

    // epilogue 1: +b1, LayerNorm per row (warp owns 8 rows), GELU -> G smem
    float bv[8], gv[8], btv[8];
#pragma unroll
    for (int j = 0; j < 8; j++) {
        int c = tx + 32 * j;
        bv[j] = b1[c]; gv[j] = lng[c]; btv[j] = lnb[c];
    }
    __syncthreads();   // done with As/Bs before overwriting with G
#pragma unroll
    for (int i = 0; i < 8; i++) {
        float s = 0.f, s2 = 0.f;
#pragma unroll
        for (int j = 0; j < 8; j++) {
            float h = acc[i][j] + bv[j];
            acc[i][j] = h; s += h; s2 += h * h;
        }
#pragma unroll
        for (int o = 16; o; o >>= 1) {
            s  += __shfl_xor_sync(0xffffffffu, s, o);
            s2 += __shfl_xor_sync(0xffffffffu, s2, o);
        }
        float mu = s * (1.f / 256.f);
        float var = s2 * (1.f / 256.f) - mu * mu;
        float rstd = rsqrtf(var + 1e-5f);
        int r = ty * 8 + i;
#pragma unroll
        for (int j = 0; j < 8; j++) {
            float nrm = (acc[i][j] - mu) * rstd * gv[j] + btv[j];
            G[r * 256 + tx + 32 * j] = gelu_exact(nrm);
        }
    }
    __syncthreads();

    // phase B: GEMM2 [64,256] x [256,128]
    float acc2[8][4];
#pragma unroll
    for (int i = 0; i < 8; i++)
#pragma unroll
        for (int j = 0; j < 4; j++) acc2[i][j] = 0.f;
    for (int kb = 0; kb < 8; kb++) {
#pragma unroll
        for (int it = 0; it < 16; it++) {
            int lin = it * 256 + tid;
            int kk = lin >> 7, c = lin & 127;
            W2s[kk * 128 + c] = W2[(size_t)(kb * 32 + kk) * HH + c];
        }
        __syncthreads();
#pragma unroll
        for (int kk = 0; kk < 32; kk++) {
            float a[8], bb[4];
#pragma unroll
            for (int i = 0; i < 8; i++) a[i] = G[(ty * 8 + i) * 256 + kb * 32 + kk];
#pragma unroll
            for (int j = 0; j < 4; j++) bb[j] = W2s[kk * 128 + tx + 32 * j];
#pragma unroll
            for (int i = 0; i < 8; i++)
#pragma unroll
                for (int j = 0; j < 4; j++) acc2[i][j] += a[i] * bb[j];
        }
        __syncthreads();
    }

    // epilogue 2: +b2, cosine relevance vs normalized topic encoding, mask
    float tqv[4], b2v[4];
#pragma unroll
    for (int j = 0; j < 4; j++) {
        int c = tx + 32 * j;
        tqv[j] = g_tenc[b * HH + c];
        b2v[j] = b2[c];
    }
#pragma unroll
    for (int i = 0; i < 8; i++) {
        float ss = 0.f, dt = 0.f;
#pragma unroll
        for (int j = 0; j < 4; j++) {
            float e = acc2[i][j] + b2v[j];
            ss += e * e; dt += e * tqv[j];
        }
#pragma unroll
        for (int o = 16; o; o >>= 1) {
            ss += __shfl_xor_sync(0xffffffffu, ss, o);
            dt += __shfl_xor_sync(0xffffffffu, dt, o);
        }
        float rel = dt / fmaxf(sqrtf(ss), 1e-12f);
        if (tx == i) g_mask[row0 + ty * 8 + i] = (rel < 0.4f) ? 1 : 0;
    }
}

// ================= K6: fused FFT -> mask multiply -> IFFT per (b,d) channel ====
// out = x + Re(c_q * ifft(mask .* fft(x))),  c_q = exp(i*sf[q]) - 1
// Radix-4: forward DIF (natural -> base4-digit-reversed), multiply in permuted
// order, mirrored inverse (digit-reversed -> natural). No bit-reversal pass.
__global__ void __launch_bounds__(256) k_fft_filter(
    const float* __restrict__ x, const float* __restrict__ sf,
    float* __restrict__ out) {
    __shared__ float twr[1024], twi[1024];
    __shared__ float re[4096], im[4096];
    int tid = threadIdx.x;
    int bd = blockIdx.x;
    int b = bd >> 8;
    int d = bd & 255;

    for (int j = tid; j < 1024; j += 256) {
        float sv, cv;
        sincospif(j * (2.0f / 4096.0f), &sv, &cv);
        twr[j] = cv; twi[j] = -sv;          // e^{-2*pi*i*j/4096}
    }

    float xreg[16];
    const float* xp = x + (size_t)b * TT * DD + d;
#pragma unroll
    for (int i = 0; i < 16; i++) {
        int t = tid + 256 * i;
        float v = xp[(size_t)t * DD];
        xreg[i] = v;
        re[t] = v; im[t] = 0.f;
    }
    __syncthreads();

    // ---- forward radix-4 DIF ----
#pragma unroll
    for (int len = 1024; len >= 1; len >>= 2) {
        int step = 1024 / len;
#pragma unroll
        for (int u = 0; u < 4; u++) {
            int k = tid + 256 * u;
            int pos = k & (len - 1);
            int i0 = ((k - pos) << 2) + pos;
            float a0r = re[i0],            a0i = im[i0];
            float a1r = re[i0 + len],      a1i = im[i0 + len];
            float a2r = re[i0 + 2 * len],  a2i = im[i0 + 2 * len];
            float a3r = re[i0 + 3 * len],  a3i = im[i0 + 3 * len];
            float s02r = a0r + a2r, s02i = a0i + a2i;
            float d02r = a0r - a2r, d02i = a0i - a2i;
            float s13r = a1r + a3r, s13i = a1i + a3i;
            float d13r = a1r - a3r, d13i = a1i - a3i;
            float y0r = s02r + s13r, y0i = s02i + s13i;
            float y1r = d02r + d13i, y1i = d02i - d13r;   // d02 - j*d13
            float y2r = s02r - s13r, y2i = s02i - s13i;
            float y3r = d02r - d13i, y3i = d02i + d13r;   // d02 + j*d13
            int e = pos * step;
            float w1r = twr[e], w1i = twi[e];
            float w2r = w1r * w1r - w1i * w1i, w2i = 2.f * w1r * w1i;
            float w3r = w1r * w2r - w1i * w2i, w3i = w1r * w2i + w1i * w2r;
            re[i0] = y0r;                               im[i0] = y0i;
            re[i0 + len]     = y1r * w1r - y1i * w1i;   im[i0 + len]     = y1r * w1i + y1i * w1r;
            re[i0 + 2 * len] = y2r * w2r - y2i * w2i;   im[i0 + 2 * len] = y2r * w2i + y2i * w2r;
            re[i0 + 3 * len] = y3r * w3r - y3i * w3i;   im[i0 + 3 * len] = y3r * w3i + y3i * w3r;
        }
        __syncthreads();
    }

    // ---- mask multiply (element p holds X[digitrev4(p)]) ----
    const unsigned char* mk = g_mask + b * TT;
#pragma unroll
    for (int i = 0; i < 16; i++) {
        int p = tid + 256 * i;
        int f = 0, pp = p;
#pragma unroll
        for (int s = 0; s < 6; s++) { f = (f << 2) | (pp & 3); pp >>= 2; }
        if (!mk[f]) { re[p] = 0.f; im[p] = 0.f; }
    }
    __syncthreads();

    // ---- inverse: mirror stages, conjugate twiddles (unnormalized, x N) ----
#pragma unroll
    for (int len = 1; len <= 1024; len <<= 2) {
        int step = 1024 / len;
#pragma unroll
        for (int u = 0; u < 4; u++) {
            int k = tid + 256 * u;
            int pos = k & (len - 1);
            int i0 = ((k - pos) << 2) + pos;
            float y0r = re[i0],           y0i = im[i0];
            float y1r = re[i0 + len],     y1i = im[i0 + len];
            float y2r = re[i0 + 2 * len], y2i = im[i0 + 2 * len];
            float y3r = re[i0 + 3 * len], y3i = im[i0 + 3 * len];
            int e = pos * step;
            float w1r = twr[e], w1i = -twi[e];
            float w2r = w1r * w1r - w1i * w1i, w2i = 2.f * w1r * w1i;
            float w3r = w1r * w2r - w1i * w2i, w3i = w1r * w2i + w1i * w2r;
            float z1r = y1r * w1r - y1i * w1i, z1i = y1r * w1i + y1i * w1r;
            float z2r = y2r * w2r - y2i * w2i, z2i = y2r * w2i + y2i * w2r;
            float z3r = y3r * w3r - y3i * w3i, z3i = y3r * w3i + y3i * w3r;
            float s02r = y0r + z2r, s02i = y0i + z2i;
            float d02r = y0r - z2r, d02i = y0i - z2i;
            float s13r = z1r + z3r, s13i = z1i + z3i;
            float d13r = z1r - z3r, d13i = z1i - z3i;
            re[i0]           = s02r + s13r;  im[i0]           = s02i + s13i;
            re[i0 + len]     = d02r - d13i;  im[i0 + len]     = d02i + d13r;  // d02 + j*d13
            re[i0 + 2 * len] = s02r - s13r;  im[i0 + 2 * len] = s02i - s13i;
            re[i0 + 3 * len] = d02r + d13i;  im[i0 + 3 * len] = d02i - d13r;  // d02 - j*d13
        }
        __syncthreads();
    }

    // ---- combine: out = x + Re(c) * Re(u)/N - Im(c) * Im(u)/N ----
    float q = sf[d & 3];
    float cr = (cosf(q) - 1.0f) * (1.0f / 4096.0f);
    float ci = sinf(q) * (1.0f / 4096.0f);
    float* op = out + (size_t)b * TT * DD + d;
#pragma unroll
    for (int i = 0; i < 16; i++) {
        int t = tid + 256 * i;
        op[(size_t)t * DD] = xreg[i] + cr * re[t] - ci * im[t];
    }
}

// ================= launch =================
extern "C" void kernel_launch(void* const* d_in, const int* in_sizes, int n_in,
                              void* d_out, int out_size) {
    const float* x    = (const float*)d_in[0];
    const float* W1   = (const float*)d_in[1];
    const float* b1   = (const float*)d_in[2];
    const float* ln_g = (const float*)d_in[3];
    const float* ln_b = (const float*)d_in[4];
    const float* W2   = (const float*)d_in[5];
    const float* b2   = (const float*)d_in[6];
    const float* tq   = (const float*)d_in[7];
    const float* sf   = (const float*)d_in[8];
    float* out = (float*)d_out;

    cudaFuncSetAttribute(k_encode_mask, cudaFuncAttributeMaxDynamicSharedMemorySize, 81920);

    k_scores<<<BT / 8, 256>>>(x, tq);
    k_softmax<<<BB, 256>>>();
    k_topic_part<<<dim3(16, BB), 256>>>(x);
    k_topic_enc<<<BB, 256>>>(W1, b1, ln_g, ln_b, W2, b2);
    k_encode_mask<<<BT / 64, 256, 81920>>>(x, W1, b1, ln_g, ln_b, W2, b2);
    k_fft_filter<<<BB * DD, 256>>>(x, sf, out);
}

// round 7
// speedup vs baseline: 1.0687x; 1.0671x over previous
#include <cuda_runtime.h>
#include <math.h>

#define BB 32
#define TT 4096
#define DD 256
#define HH 128
#define BT (BB*TT)

// ---- scratch (device globals; no allocation) ----
__device__ float g_scores[BT];           // scores, normalized to weights in place
__device__ float g_part[16*BB*DD];       // main_topic partial sums
__device__ float g_tenc[BB*HH];          // normalized topic encoding
__device__ unsigned char g_mask[BT];     // irrelevance mask per (b, freq)

__device__ __forceinline__ float gelu_exact(float v) {
    return 0.5f * v * (1.0f + erff(v * 0.70710678118654752f));
}

// ---- packed f32x2 helpers (sm_103a FFMA2 path; ptxas never emits this) ----
__device__ __forceinline__ unsigned long long pk2(float lo, float hi) {
    unsigned long long r;
    asm("mov.b64 %0, {%1,%2};" : "=l"(r) : "f"(lo), "f"(hi));
    return r;
}
__device__ __forceinline__ void upk2(unsigned long long v, float& lo, float& hi) {
    asm("mov.b64 {%0,%1}, %2;" : "=f"(lo), "=f"(hi) : "l"(v));
}
#define FMA2(d, a, b, c) asm("fma.rn.f32x2 %0, %1, %2, %3;" : "=l"(d) : "l"(a), "l"(b), "l"(c))

// ================= K1: scores[b,t] = dot(q, x[b,t]) / TEMP =================
__global__ void __launch_bounds__(256) k_scores(const float* __restrict__ x,
                                                const float* __restrict__ tq) {
    int warp = (blockIdx.x * blockDim.x + threadIdx.x) >> 5;
    int lane = threadIdx.x & 31;
    if (warp >= BT) return;
    const float* xr = x + (size_t)warp * DD;
    float s = 0.f;
#pragma unroll
    for (int i = 0; i < 8; i++) {
        int c = lane + 32 * i;
        s += xr[c] * __ldg(tq + c);
    }
#pragma unroll
    for (int o = 16; o; o >>= 1) s += __shfl_xor_sync(0xffffffffu, s, o);
    if (lane == 0) g_scores[warp] = s * 2.0f;   // 1/TEMPERATURE = 2
}

// ================= K2: per-b softmax over T, in place =================
__global__ void __launch_bounds__(256) k_softmax() {
    int b = blockIdx.x;
    int tid = threadIdx.x;
    __shared__ float red[256];
    float* s = g_scores + b * TT;
    float v[16];
    float mx = -1e30f;
#pragma unroll
    for (int i = 0; i < 16; i++) { v[i] = s[tid + 256 * i]; mx = fmaxf(mx, v[i]); }
    red[tid] = mx; __syncthreads();
    for (int o = 128; o; o >>= 1) { if (tid < o) red[tid] = fmaxf(red[tid], red[tid + o]); __syncthreads(); }
    mx = red[0]; __syncthreads();
    float sum = 0.f;
#pragma unroll
    for (int i = 0; i < 16; i++) { v[i] = expf(v[i] - mx); sum += v[i]; }
    red[tid] = sum; __syncthreads();
    for (int o = 128; o; o >>= 1) { if (tid < o) red[tid] += red[tid + o]; __syncthreads(); }
    float inv = 1.0f / red[0];
#pragma unroll
    for (int i = 0; i < 16; i++) s[tid + 256 * i] = v[i] * inv;
}

// ================= K3: main_topic partials over t-chunks =================
__global__ void __launch_bounds__(256) k_topic_part(const float* __restrict__ x) {
    int chunk = blockIdx.x;          // 0..15
    int b = blockIdx.y;              // 0..31
    int d = threadIdx.x;             // 0..255
    __shared__ float w[256];
    int t0 = chunk * 256;
    w[d] = g_scores[b * TT + t0 + d];
    __syncthreads();
    float acc = 0.f;
    const float* xp = x + ((size_t)b * TT + t0) * DD + d;
#pragma unroll 4
    for (int t = 0; t < 256; t++) acc += w[t] * xp[(size_t)t * DD];
    g_part[(chunk * BB + b) * DD + d] = acc;
}

// ================= K4: encode main_topic, normalize =================
__global__ void __launch_bounds__(256) k_topic_enc(
    const float* __restrict__ W1, const float* __restrict__ b1,
    const float* __restrict__ lng, const float* __restrict__ lnb,
    const float* __restrict__ W2, const float* __restrict__ b2) {
    int b = blockIdx.x, tid = threadIdx.x;
    __shared__ float mt[256], red[256], red2[256], gbuf[256];
    float acc = 0.f;
#pragma unroll
    for (int c = 0; c < 16; c++) acc += g_part[(c * BB + b) * DD + tid];
    mt[tid] = acc;
    __syncthreads();
    float h = b1[tid];
    for (int k = 0; k < DD; k++) h += mt[k] * W1[k * DD + tid];
    red[tid] = h; red2[tid] = h * h;
    __syncthreads();
    for (int o = 128; o; o >>= 1) {
        if (tid < o) { red[tid] += red[tid + o]; red2[tid] += red2[tid + o]; }
        __syncthreads();
    }
    float mu = red[0] * (1.f / 256.f);
    float var = red2[0] * (1.f / 256.f) - mu * mu;
    float n = (h - mu) * rsqrtf(var + 1e-5f) * lng[tid] + lnb[tid];
    float g = gelu_exact(n);
    __syncthreads();
    gbuf[tid] = g;
    __syncthreads();
    float e = 0.f;
    if (tid < HH) {
        e = b2[tid];
        for (int k = 0; k < DD; k++) e += gbuf[k] * W2[k * HH + tid];
    }
    red[tid] = (tid < HH) ? e * e : 0.f;
    __syncthreads();
    for (int o = 128; o; o >>= 1) { if (tid < o) red[tid] += red[tid + o]; __syncthreads(); }
    if (tid < HH) {
        float nrm = fmaxf(sqrtf(red[0]), 1e-12f);
        g_tenc[b * HH + tid] = e / nrm;
    }
}

// ================= K5: encoder GEMMs (fma.rn.f32x2) + LN + GELU + mask =======
// 64 rows per CTA, 256 threads. Thread tx owns adjacent column pairs
// (2tx+64j, 2tx+64j+1): B fragments load as conflict-free LDS.64, A broadcasts
// pack once per kk, accumulators are packed f32x2. Per-column summation order
// is identical to the scalar baseline (bit-identical results).
__global__ void __launch_bounds__(256) k_encode_mask(
    const float* __restrict__ x, const float* __restrict__ W1,
    const float* __restrict__ b1, const float* __restrict__ lng,
    const float* __restrict__ lnb, const float* __restrict__ W2,
    const float* __restrict__ b2) {
    extern __shared__ float sm[];
    float* As = sm;                  // [16][65]  (phase A)
    float* Bs = sm + 16 * 65;        // [16][256] (phase A)
    float* G   = sm;                 // [64][256] (phase B, aliases)
    float* W2s = sm + 64 * 256;      // [32][128] (phase B)

    int tid = threadIdx.x;
    int tx = tid & 31, ty = tid >> 5;        // 32 x 8
    int row0 = blockIdx.x * 64;
    int b = row0 >> 12;                       // T = 4096

    unsigned long long acc[8][4];
#pragma unroll
    for (int i = 0; i < 8; i++)
#pragma unroll
        for (int j = 0; j < 4; j++) acc[i][j] = 0ULL;

    for (int kb = 0; kb < 16; kb++) {
        int k0 = kb * 16;
        __syncthreads();
#pragma unroll
        for (int it = 0; it < 4; it++) {
            int lin = it * 256 + tid;
            int r = lin >> 4, kk = lin & 15;
            As[kk * 65 + r] = x[((size_t)(row0 + r)) * DD + k0 + kk];
        }
#pragma unroll
        for (int it = 0; it < 16; it++)
            Bs[it * 256 + tid] = W1[(size_t)(k0 + it) * DD + tid];
        __syncthreads();
#pragma unroll
        for (int kk = 0; kk < 16; kk++) {
            unsigned long long A2[8], bb[4];
#pragma unroll
            for (int i = 0; i < 8; i++) {
                float a = As[kk * 65 + ty * 8 + i];
                A2[i] = pk2(a, a);
            }
#pragma unroll
            for (int j = 0; j < 4; j++)
                bb[j] = *(const unsigned long long*)&Bs[kk * 256 + 2 * tx + 64 * j];
#pragma unroll
            for (int i = 0; i < 8; i++)
#pragma unroll
                for (int j = 0; j < 4; j++)
                    FMA2(acc[i][j], A2[i], bb[j], acc[i][j]);
        }
    }

    // epilogue 1: +b1, LayerNorm per row (warp owns 8 rows), GELU -> G smem
    float bv[8], gv[8], btv[8];
#pragma unroll
    for (int j = 0; j < 4; j++) {
        int c = 2 * tx + 64 * j;
        float2 t;
        t = *(const float2*)(b1 + c);  bv[2 * j] = t.x;  bv[2 * j + 1] = t.y;
        t = *(const float2*)(lng + c); gv[2 * j] = t.x;  gv[2 * j + 1] = t.y;
        t = *(const float2*)(lnb + c); btv[2 * j] = t.x; btv[2 * j + 1] = t.y;
    }
    __syncthreads();   // done with As/Bs before overwriting with G
#pragma unroll
    for (int i = 0; i < 8; i++) {
        float h[8];
#pragma unroll
        for (int j = 0; j < 4; j++) {
            float lo, hi; upk2(acc[i][j], lo, hi);
            h[2 * j] = lo + bv[2 * j];
            h[2 * j + 1] = hi + bv[2 * j + 1];
        }
        float s = 0.f, s2 = 0.f;
#pragma unroll
        for (int j = 0; j < 8; j++) { s += h[j]; s2 += h[j] * h[j]; }
#pragma unroll
        for (int o = 16; o; o >>= 1) {
            s  += __shfl_xor_sync(0xffffffffu, s, o);
            s2 += __shfl_xor_sync(0xffffffffu, s2, o);
        }
        float mu = s * (1.f / 256.f);
        float var = s2 * (1.f / 256.f) - mu * mu;
        float rstd = rsqrtf(var + 1e-5f);
        int r = ty * 8 + i;
#pragma unroll
        for (int j = 0; j < 4; j++) {
            float g0 = gelu_exact((h[2 * j] - mu) * rstd * gv[2 * j] + btv[2 * j]);
            float g1 = gelu_exact((h[2 * j + 1] - mu) * rstd * gv[2 * j + 1] + btv[2 * j + 1]);
            *(float2*)&G[r * 256 + 2 * tx + 64 * j] = make_float2(g0, g1);
        }
    }
    __syncthreads();

    // phase B: GEMM2 [64,256] x [256,128], thread owns col pairs (2tx, 2tx+1),
    // (2tx+64, 2tx+65)
    unsigned long long acc2[8][2];
#pragma unroll
    for (int i = 0; i < 8; i++) { acc2[i][0] = 0ULL; acc2[i][1] = 0ULL; }
    for (int kb = 0; kb < 8; kb++) {
#pragma unroll
        for (int it = 0; it < 16; it++) {
            int lin = it * 256 + tid;
            int kk = lin >> 7, c = lin & 127;
            W2s[kk * 128 + c] = W2[(size_t)(kb * 32 + kk) * HH + c];
        }
        __syncthreads();
#pragma unroll
        for (int kk = 0; kk < 32; kk++) {
            unsigned long long A2[8], bb[2];
#pragma unroll
            for (int i = 0; i < 8; i++) {
                float a = G[(ty * 8 + i) * 256 + kb * 32 + kk];
                A2[i] = pk2(a, a);
            }
            bb[0] = *(const unsigned long long*)&W2s[kk * 128 + 2 * tx];
            bb[1] = *(const unsigned long long*)&W2s[kk * 128 + 2 * tx + 64];
#pragma unroll
            for (int i = 0; i < 8; i++) {
                FMA2(acc2[i][0], A2[i], bb[0], acc2[i][0]);
                FMA2(acc2[i][1], A2[i], bb[1], acc2[i][1]);
            }
        }
        __syncthreads();
    }

    // epilogue 2: +b2, cosine relevance vs normalized topic encoding, mask
    float tqv[4], b2v[4];
#pragma unroll
    for (int j = 0; j < 2; j++) {
        int c = 2 * tx + 64 * j;
        float2 t;
        t = *(const float2*)(&g_tenc[b * HH + c]); tqv[2 * j] = t.x; tqv[2 * j + 1] = t.y;
        t = *(const float2*)(b2 + c);              b2v[2 * j] = t.x; b2v[2 * j + 1] = t.y;
    }
#pragma unroll
    for (int i = 0; i < 8; i++) {
        float e[4];
        { float lo, hi; upk2(acc2[i][0], lo, hi); e[0] = lo + b2v[0]; e[1] = hi + b2v[1]; }
        { float lo, hi; upk2(acc2[i][1], lo, hi); e[2] = lo + b2v[2]; e[3] = hi + b2v[3]; }
        float ss = 0.f, dt = 0.f;
#pragma unroll
        for (int j = 0; j < 4; j++) { ss += e[j] * e[j]; dt += e[j] * tqv[j]; }
#pragma unroll
        for (int o = 16; o; o >>= 1) {
            ss += __shfl_xor_sync(0xffffffffu, ss, o);
            dt += __shfl_xor_sync(0xffffffffu, dt, o);
        }
        float rel = dt / fmaxf(sqrtf(ss), 1e-12f);
        if (tx == i) g_mask[row0 + ty * 8 + i] = (rel < 0.4f) ? 1 : 0;
    }
}

// ================= K6: fused FFT -> mask multiply -> IFFT per (b,d) channel ====
// out = x + Re(c_q * ifft(mask .* fft(x))),  c_q = exp(i*sf[q]) - 1
// Radix-4: forward DIF (natural -> base4-digit-reversed), multiply in permuted
// order, mirrored inverse (digit-reversed -> natural). No bit-reversal pass.
__global__ void __launch_bounds__(256) k_fft_filter(
    const float* __restrict__ x, const float* __restrict__ sf,
    float* __restrict__ out) {
    __shared__ float twr[1024], twi[1024];
    __shared__ float re[4096], im[4096];
    int tid = threadIdx.x;
    int bd = blockIdx.x;
    int b = bd >> 8;
    int d = bd & 255;

    for (int j = tid; j < 1024; j += 256) {
        float sv, cv;
        sincospif(j * (2.0f / 4096.0f), &sv, &cv);
        twr[j] = cv; twi[j] = -sv;          // e^{-2*pi*i*j/4096}
    }

    float xreg[16];
    const float* xp = x + (size_t)b * TT * DD + d;
#pragma unroll
    for (int i = 0; i < 16; i++) {
        int t = tid + 256 * i;
        float v = xp[(size_t)t * DD];
        xreg[i] = v;
        re[t] = v; im[t] = 0.f;
    }
    __syncthreads();

    // ---- forward radix-4 DIF ----
#pragma unroll
    for (int len = 1024; len >= 1; len >>= 2) {
        int step = 1024 / len;
#pragma unroll
        for (int u = 0; u < 4; u++) {
            int k = tid + 256 * u;
            int pos = k & (len - 1);
            int i0 = ((k - pos) << 2) + pos;
            float a0r = re[i0],            a0i = im[i0];
            float a1r = re[i0 + len],      a1i = im[i0 + len];
            float a2r = re[i0 + 2 * len],  a2i = im[i0 + 2 * len];
            float a3r = re[i0 + 3 * len],  a3i = im[i0 + 3 * len];
            float s02r = a0r + a2r, s02i = a0i + a2i;
            float d02r = a0r - a2r, d02i = a0i - a2i;
            float s13r = a1r + a3r, s13i = a1i + a3i;
            float d13r = a1r - a3r, d13i = a1i - a3i;
            float y0r = s02r + s13r, y0i = s02i + s13i;
            float y1r = d02r + d13i, y1i = d02i - d13r;   // d02 - j*d13
            float y2r = s02r - s13r, y2i = s02i - s13i;
            float y3r = d02r - d13i, y3i = d02i + d13r;   // d02 + j*d13
            int e = pos * step;
            float w1r = twr[e], w1i = twi[e];
            float w2r = w1r * w1r - w1i * w1i, w2i = 2.f * w1r * w1i;
            float w3r = w1r * w2r - w1i * w2i, w3i = w1r * w2i + w1i * w2r;
            re[i0] = y0r;                               im[i0] = y0i;
            re[i0 + len]     = y1r * w1r - y1i * w1i;   im[i0 + len]     = y1r * w1i + y1i * w1r;
            re[i0 + 2 * len] = y2r * w2r - y2i * w2i;   im[i0 + 2 * len] = y2r * w2i + y2i * w2r;
            re[i0 + 3 * len] = y3r * w3r - y3i * w3i;   im[i0 + 3 * len] = y3r * w3i + y3i * w3r;
        }
        __syncthreads();
    }

    // ---- mask multiply (element p holds X[digitrev4(p)]) ----
    const unsigned char* mk = g_mask + b * TT;
#pragma unroll
    for (int i = 0; i < 16; i++) {
        int p = tid + 256 * i;
        int f = 0, pp = p;
#pragma unroll
        for (int s = 0; s < 6; s++) { f = (f << 2) | (pp & 3); pp >>= 2; }
        if (!mk[f]) { re[p] = 0.f; im[p] = 0.f; }
    }
    __syncthreads();

    // ---- inverse: mirror stages, conjugate twiddles (unnormalized, x N) ----
#pragma unroll
    for (int len = 1; len <= 1024; len <<= 2) {
        int step = 1024 / len;
#pragma unroll
        for (int u = 0; u < 4; u++) {
            int k = tid + 256 * u;
            int pos = k & (len - 1);
            int i0 = ((k - pos) << 2) + pos;
            float y0r = re[i0],           y0i = im[i0];
            float y1r = re[i0 + len],     y1i = im[i0 + len];
            float y2r = re[i0 + 2 * len], y2i = im[i0 + 2 * len];
            float y3r = re[i0 + 3 * len], y3i = im[i0 + 3 * len];
            int e = pos * step;
            float w1r = twr[e], w1i = -twi[e];
            float w2r = w1r * w1r - w1i * w1i, w2i = 2.f * w1r * w1i;
            float w3r = w1r * w2r - w1i * w2i, w3i = w1r * w2i + w1i * w2r;
            float z1r = y1r * w1r - y1i * w1i, z1i = y1r * w1i + y1i * w1r;
            float z2r = y2r * w2r - y2i * w2i, z2i = y2r * w2i + y2i * w2r;
            float z3r = y3r * w3r - y3i * w3i, z3i = y3r * w3i + y3i * w3r;
            float s02r = y0r + z2r, s02i = y0i + z2i;
            float d02r = y0r - z2r, d02i = y0i - z2i;
            float s13r = z1r + z3r, s13i = z1i + z3i;
            float d13r = z1r - z3r, d13i = z1i - z3i;
            re[i0]           = s02r + s13r;  im[i0]           = s02i + s13i;
            re[i0 + len]     = d02r - d13i;  im[i0 + len]     = d02i + d13r;  // d02 + j*d13
            re[i0 + 2 * len] = s02r - s13r;  im[i0 + 2 * len] = s02i - s13i;
            re[i0 + 3 * len] = d02r + d13i;  im[i0 + 3 * len] = d02i - d13r;  // d02 - j*d13
        }
        __syncthreads();
    }

    // ---- combine: out = x + Re(c) * Re(u)/N - Im(c) * Im(u)/N ----
    float q = sf[d & 3];
    float cr = (cosf(q) - 1.0f) * (1.0f / 4096.0f);
    float ci = sinf(q) * (1.0f / 4096.0f);
    float* op = out + (size_t)b * TT * DD + d;
#pragma unroll
    for (int i = 0; i < 16; i++) {
        int t = tid + 256 * i;
        op[(size_t)t * DD] = xreg[i] + cr * re[t] - ci * im[t];
    }
}

// ================= launch =================
extern "C" void kernel_launch(void* const* d_in, const int* in_sizes, int n_in,
                              void* d_out, int out_size) {
    const float* x    = (const float*)d_in[0];
    const float* W1   = (const float*)d_in[1];
    const float* b1   = (const float*)d_in[2];
    const float* ln_g = (const float*)d_in[3];
    const float* ln_b = (const float*)d_in[4];
    const float* W2   = (const float*)d_in[5];
    const float* b2   = (const float*)d_in[6];
    const float* tq   = (const float*)d_in[7];
    const float* sf   = (const float*)d_in[8];
    float* out = (float*)d_out;

    cudaFuncSetAttribute(k_encode_mask, cudaFuncAttributeMaxDynamicSharedMemorySize, 81920);

    k_scores<<<BT / 8, 256>>>(x, tq);
    k_softmax<<<BB, 256>>>();
    k_topic_part<<<dim3(16, BB), 256>>>(x);
    k_topic_enc<<<BB, 256>>>(W1, b1, ln_g, ln_b, W2, b2);
    k_encode_mask<<<BT / 64, 256, 81920>>>(x, W1, b1, ln_g, ln_b, W2, b2);
    k_fft_filter<<<BB * DD, 256>>>(x, sf, out);
}

// round 8
// speedup vs baseline: 1.4618x; 1.3678x over previous
#include <cuda_runtime.h>
#include <math.h>

#define BB 32
#define TT 4096
#define DD 256
#define HH 128
#define BT (BB*TT)

// ---- scratch (device globals; no allocation) ----
__device__ float g_scores[BT];           // scores, normalized to weights in place
__device__ float g_part[16*BB*DD];       // main_topic partial sums
__device__ float g_tenc[BB*HH];          // normalized topic encoding
__device__ unsigned char g_mask[BT];     // irrelevance mask per (b, freq)

__device__ __forceinline__ float gelu_exact(float v) {
    return 0.5f * v * (1.0f + erff(v * 0.70710678118654752f));
}

// ---- packed f32x2 helpers (sm_103a FFMA2 path; ptxas never emits this) ----
__device__ __forceinline__ unsigned long long pk2(float lo, float hi) {
    unsigned long long r;
    asm("mov.b64 %0, {%1,%2};" : "=l"(r) : "f"(lo), "f"(hi));
    return r;
}
__device__ __forceinline__ void upk2(unsigned long long v, float& lo, float& hi) {
    asm("mov.b64 {%0,%1}, %2;" : "=f"(lo), "=f"(hi) : "l"(v));
}
#define FMA2(d, a, b, c) asm("fma.rn.f32x2 %0, %1, %2, %3;" : "=l"(d) : "l"(a), "l"(b), "l"(c))

// ================= K1: scores[b,t] = dot(q, x[b,t]) / TEMP =================
__global__ void __launch_bounds__(256) k_scores(const float* __restrict__ x,
                                                const float* __restrict__ tq) {
    int warp = (blockIdx.x * blockDim.x + threadIdx.x) >> 5;
    int lane = threadIdx.x & 31;
    if (warp >= BT) return;
    const float* xr = x + (size_t)warp * DD;
    float s = 0.f;
#pragma unroll
    for (int i = 0; i < 8; i++) {
        int c = lane + 32 * i;
        s += xr[c] * __ldg(tq + c);
    }
#pragma unroll
    for (int o = 16; o; o >>= 1) s += __shfl_xor_sync(0xffffffffu, s, o);
    if (lane == 0) g_scores[warp] = s * 2.0f;   // 1/TEMPERATURE = 2
}

// ================= K2: per-b softmax over T, in place =================
__global__ void __launch_bounds__(256) k_softmax() {
    int b = blockIdx.x;
    int tid = threadIdx.x;
    __shared__ float red[256];
    float* s = g_scores + b * TT;
    float v[16];
    float mx = -1e30f;
#pragma unroll
    for (int i = 0; i < 16; i++) { v[i] = s[tid + 256 * i]; mx = fmaxf(mx, v[i]); }
    red[tid] = mx; __syncthreads();
    for (int o = 128; o; o >>= 1) { if (tid < o) red[tid] = fmaxf(red[tid], red[tid + o]); __syncthreads(); }
    mx = red[0]; __syncthreads();
    float sum = 0.f;
#pragma unroll
    for (int i = 0; i < 16; i++) { v[i] = expf(v[i] - mx); sum += v[i]; }
    red[tid] = sum; __syncthreads();
    for (int o = 128; o; o >>= 1) { if (tid < o) red[tid] += red[tid + o]; __syncthreads(); }
    float inv = 1.0f / red[0];
#pragma unroll
    for (int i = 0; i < 16; i++) s[tid + 256 * i] = v[i] * inv;
}

// ================= K3: main_topic partials over t-chunks =================
__global__ void __launch_bounds__(256) k_topic_part(const float* __restrict__ x) {
    int chunk = blockIdx.x;          // 0..15
    int b = blockIdx.y;              // 0..31
    int d = threadIdx.x;             // 0..255
    __shared__ float w[256];
    int t0 = chunk * 256;
    w[d] = g_scores[b * TT + t0 + d];
    __syncthreads();
    float acc = 0.f;
    const float* xp = x + ((size_t)b * TT + t0) * DD + d;
#pragma unroll 4
    for (int t = 0; t < 256; t++) acc += w[t] * xp[(size_t)t * DD];
    g_part[(chunk * BB + b) * DD + d] = acc;
}

// ================= K4: encode main_topic, normalize =================
__global__ void __launch_bounds__(256) k_topic_enc(
    const float* __restrict__ W1, const float* __restrict__ b1,
    const float* __restrict__ lng, const float* __restrict__ lnb,
    const float* __restrict__ W2, const float* __restrict__ b2) {
    int b = blockIdx.x, tid = threadIdx.x;
    __shared__ float mt[256], red[256], red2[256], gbuf[256];
    float acc = 0.f;
#pragma unroll
    for (int c = 0; c < 16; c++) acc += g_part[(c * BB + b) * DD + tid];
    mt[tid] = acc;
    __syncthreads();
    float h = b1[tid];
    for (int k = 0; k < DD; k++) h += mt[k] * W1[k * DD + tid];
    red[tid] = h; red2[tid] = h * h;
    __syncthreads();
    for (int o = 128; o; o >>= 1) {
        if (tid < o) { red[tid] += red[tid + o]; red2[tid] += red2[tid + o]; }
        __syncthreads();
    }
    float mu = red[0] * (1.f / 256.f);
    float var = red2[0] * (1.f / 256.f) - mu * mu;
    float n = (h - mu) * rsqrtf(var + 1e-5f) * lng[tid] + lnb[tid];
    float g = gelu_exact(n);
    __syncthreads();
    gbuf[tid] = g;
    __syncthreads();
    float e = 0.f;
    if (tid < HH) {
        e = b2[tid];
        for (int k = 0; k < DD; k++) e += gbuf[k] * W2[k * HH + tid];
    }
    red[tid] = (tid < HH) ? e * e : 0.f;
    __syncthreads();
    for (int o = 128; o; o >>= 1) { if (tid < o) red[tid] += red[tid + o]; __syncthreads(); }
    if (tid < HH) {
        float nrm = fmaxf(sqrtf(red[0]), 1e-12f);
        g_tenc[b * HH + tid] = e / nrm;
    }
}

// ================= K5: encoder GEMMs (fma.rn.f32x2) + LN + GELU + mask =======
__global__ void __launch_bounds__(256) k_encode_mask(
    const float* __restrict__ x, const float* __restrict__ W1,
    const float* __restrict__ b1, const float* __restrict__ lng,
    const float* __restrict__ lnb, const float* __restrict__ W2,
    const float* __restrict__ b2) {
    extern __shared__ float sm[];
    float* As = sm;                  // [16][65]  (phase A)
    float* Bs = sm + 16 * 65;        // [16][256] (phase A)
    float* G   = sm;                 // [64][256] (phase B, aliases)
    float* W2s = sm + 64 * 256;      // [32][128] (phase B)

    int tid = threadIdx.x;
    int tx = tid & 31, ty = tid >> 5;        // 32 x 8
    int row0 = blockIdx.x * 64;
    int b = row0 >> 12;                       // T = 4096

    unsigned long long acc[8][4];
#pragma unroll
    for (int i = 0; i < 8; i++)
#pragma unroll
        for (int j = 0; j < 4; j++) acc[i][j] = 0ULL;

    for (int kb = 0; kb < 16; kb++) {
        int k0 = kb * 16;
        __syncthreads();
#pragma unroll
        for (int it = 0; it < 4; it++) {
            int lin = it * 256 + tid;
            int r = lin >> 4, kk = lin & 15;
            As[kk * 65 + r] = x[((size_t)(row0 + r)) * DD + k0 + kk];
        }
#pragma unroll
        for (int it = 0; it < 16; it++)
            Bs[it * 256 + tid] = W1[(size_t)(k0 + it) * DD + tid];
        __syncthreads();
#pragma unroll
        for (int kk = 0; kk < 16; kk++) {
            unsigned long long A2[8], bb[4];
#pragma unroll
            for (int i = 0; i < 8; i++) {
                float a = As[kk * 65 + ty * 8 + i];
                A2[i] = pk2(a, a);
            }
#pragma unroll
            for (int j = 0; j < 4; j++)
                bb[j] = *(const unsigned long long*)&Bs[kk * 256 + 2 * tx + 64 * j];
#pragma unroll
            for (int i = 0; i < 8; i++)
#pragma unroll
                for (int j = 0; j < 4; j++)
                    FMA2(acc[i][j], A2[i], bb[j], acc[i][j]);
        }
    }

    // epilogue 1: +b1, LayerNorm per row (warp owns 8 rows), GELU -> G smem
    float bv[8], gv[8], btv[8];
#pragma unroll
    for (int j = 0; j < 4; j++) {
        int c = 2 * tx + 64 * j;
        float2 t;
        t = *(const float2*)(b1 + c);  bv[2 * j] = t.x;  bv[2 * j + 1] = t.y;
        t = *(const float2*)(lng + c); gv[2 * j] = t.x;  gv[2 * j + 1] = t.y;
        t = *(const float2*)(lnb + c); btv[2 * j] = t.x; btv[2 * j + 1] = t.y;
    }
    __syncthreads();   // done with As/Bs before overwriting with G
#pragma unroll
    for (int i = 0; i < 8; i++) {
        float h[8];
#pragma unroll
        for (int j = 0; j < 4; j++) {
            float lo, hi; upk2(acc[i][j], lo, hi);
            h[2 * j] = lo + bv[2 * j];
            h[2 * j + 1] = hi + bv[2 * j + 1];
        }
        float s = 0.f, s2 = 0.f;
#pragma unroll
        for (int j = 0; j < 8; j++) { s += h[j]; s2 += h[j] * h[j]; }
#pragma unroll
        for (int o = 16; o; o >>= 1) {
            s  += __shfl_xor_sync(0xffffffffu, s, o);
            s2 += __shfl_xor_sync(0xffffffffu, s2, o);
        }
        float mu = s * (1.f / 256.f);
        float var = s2 * (1.f / 256.f) - mu * mu;
        float rstd = rsqrtf(var + 1e-5f);
        int r = ty * 8 + i;
#pragma unroll
        for (int j = 0; j < 4; j++) {
            float g0 = gelu_exact((h[2 * j] - mu) * rstd * gv[2 * j] + btv[2 * j]);
            float g1 = gelu_exact((h[2 * j + 1] - mu) * rstd * gv[2 * j + 1] + btv[2 * j + 1]);
            *(float2*)&G[r * 256 + 2 * tx + 64 * j] = make_float2(g0, g1);
        }
    }
    __syncthreads();

    // phase B: GEMM2 [64,256] x [256,128]
    unsigned long long acc2[8][2];
#pragma unroll
    for (int i = 0; i < 8; i++) { acc2[i][0] = 0ULL; acc2[i][1] = 0ULL; }
    for (int kb = 0; kb < 8; kb++) {
#pragma unroll
        for (int it = 0; it < 16; it++) {
            int lin = it * 256 + tid;
            int kk = lin >> 7, c = lin & 127;
            W2s[kk * 128 + c] = W2[(size_t)(kb * 32 + kk) * HH + c];
        }
        __syncthreads();
#pragma unroll
        for (int kk = 0; kk < 32; kk++) {
            unsigned long long A2[8], bb[2];
#pragma unroll
            for (int i = 0; i < 8; i++) {
                float a = G[(ty * 8 + i) * 256 + kb * 32 + kk];
                A2[i] = pk2(a, a);
            }
            bb[0] = *(const unsigned long long*)&W2s[kk * 128 + 2 * tx];
            bb[1] = *(const unsigned long long*)&W2s[kk * 128 + 2 * tx + 64];
#pragma unroll
            for (int i = 0; i < 8; i++) {
                FMA2(acc2[i][0], A2[i], bb[0], acc2[i][0]);
                FMA2(acc2[i][1], A2[i], bb[1], acc2[i][1]);
            }
        }
        __syncthreads();
    }

    // epilogue 2: +b2, cosine relevance vs normalized topic encoding, mask
    float tqv[4], b2v[4];
#pragma unroll
    for (int j = 0; j < 2; j++) {
        int c = 2 * tx + 64 * j;
        float2 t;
        t = *(const float2*)(&g_tenc[b * HH + c]); tqv[2 * j] = t.x; tqv[2 * j + 1] = t.y;
        t = *(const float2*)(b2 + c);              b2v[2 * j] = t.x; b2v[2 * j + 1] = t.y;
    }
#pragma unroll
    for (int i = 0; i < 8; i++) {
        float e[4];
        { float lo, hi; upk2(acc2[i][0], lo, hi); e[0] = lo + b2v[0]; e[1] = hi + b2v[1]; }
        { float lo, hi; upk2(acc2[i][1], lo, hi); e[2] = lo + b2v[2]; e[3] = hi + b2v[3]; }
        float ss = 0.f, dt = 0.f;
#pragma unroll
        for (int j = 0; j < 4; j++) { ss += e[j] * e[j]; dt += e[j] * tqv[j]; }
#pragma unroll
        for (int o = 16; o; o >>= 1) {
            ss += __shfl_xor_sync(0xffffffffu, ss, o);
            dt += __shfl_xor_sync(0xffffffffu, dt, o);
        }
        float rel = dt / fmaxf(sqrtf(ss), 1e-12f);
        if (tx == i) g_mask[row0 + ty * 8 + i] = (rel < 0.4f) ? 1 : 0;
    }
}

// ================= K6: radix-16 fused FFT -> mask -> IFFT per (b,d) =========
// 4096 = 16^3. Forward: DFT16(stride 256, tw W^(t r)) -> DFT16(stride 16,
// tw W256^(p u)) -> DFT16 (registers). Mask in-register, inverse mirrors.
// out = x + Re(c_q * ifft(mask .* fft(x))), c_q = exp(i*sf[q]) - 1.
__device__ __forceinline__ float2 cmulf(float2 a, float2 b) {
    return make_float2(a.x * b.x - a.y * b.y, a.x * b.y + a.y * b.x);
}

// 16-pt DFT, input natural order a[j], output index m lands in slot PRM(m).
template<bool INV>
__device__ __forceinline__ void dft16(float2* a) {
#pragma unroll
    for (int j0 = 0; j0 < 4; j0++) {                 // radix-4 over j = j0 + 4*jq
        float2 A0 = a[j0], A1 = a[j0 + 4], A2 = a[j0 + 8], A3 = a[j0 + 12];
        float s02r = A0.x + A2.x, s02i = A0.y + A2.y;
        float d02r = A0.x - A2.x, d02i = A0.y - A2.y;
        float s13r = A1.x + A3.x, s13i = A1.y + A3.y;
        float d13r = A1.x - A3.x, d13i = A1.y - A3.y;
        a[j0]     = make_float2(s02r + s13r, s02i + s13i);
        a[j0 + 8] = make_float2(s02r - s13r, s02i - s13i);
        if (!INV) {
            a[j0 + 4]  = make_float2(d02r + d13i, d02i - d13r);
            a[j0 + 12] = make_float2(d02r - d13i, d02i + d13r);
        } else {
            a[j0 + 4]  = make_float2(d02r - d13i, d02i + d13r);
            a[j0 + 12] = make_float2(d02r + d13i, d02i - d13r);
        }
    }
    // twiddle W16^{j0*r0} at slot j0 + 4*r0
    const float C1 = 0.9238795325112867f, S1 = 0.3826834323650898f, R2 = 0.7071067811865476f;
    const float SG = INV ? 1.f : -1.f;
    a[5]  = cmulf(a[5],  make_float2( C1,  SG * S1));
    a[6]  = cmulf(a[6],  make_float2( R2,  SG * R2));
    a[7]  = cmulf(a[7],  make_float2( S1,  SG * C1));
    a[9]  = cmulf(a[9],  make_float2( R2,  SG * R2));
    a[10] = cmulf(a[10], make_float2( 0.f, SG * 1.f));
    a[11] = cmulf(a[11], make_float2(-R2,  SG * R2));
    a[13] = cmulf(a[13], make_float2( S1,  SG * C1));
    a[14] = cmulf(a[14], make_float2(-R2,  SG * R2));
    a[15] = cmulf(a[15], make_float2(-C1, -SG * S1));
#pragma unroll
    for (int r0 = 0; r0 < 4; r0++) {                 // radix-4 within groups of 4
        float2 A0 = a[4 * r0], A1 = a[4 * r0 + 1], A2 = a[4 * r0 + 2], A3 = a[4 * r0 + 3];
        float s02r = A0.x + A2.x, s02i = A0.y + A2.y;
        float d02r = A0.x - A2.x, d02i = A0.y - A2.y;
        float s13r = A1.x + A3.x, s13i = A1.y + A3.y;
        float d13r = A1.x - A3.x, d13i = A1.y - A3.y;
        a[4 * r0]     = make_float2(s02r + s13r, s02i + s13i);
        a[4 * r0 + 2] = make_float2(s02r - s13r, s02i - s13i);
        if (!INV) {
            a[4 * r0 + 1] = make_float2(d02r + d13i, d02i - d13r);
            a[4 * r0 + 3] = make_float2(d02r - d13i, d02i + d13r);
        } else {
            a[4 * r0 + 1] = make_float2(d02r - d13i, d02i + d13r);
            a[4 * r0 + 3] = make_float2(d02r + d13i, d02i - d13r);
        }
    }
}
#define PRM(m) (4 * ((m) & 3) + ((m) >> 2))   // involution: base-4 digit swap
#define SWP(i) ((i) + ((i) >> 4))             // pad 1 float2 per 16

__global__ void __launch_bounds__(256) k_fft_filter(
    const float* __restrict__ x, const float* __restrict__ sf,
    float* __restrict__ out) {
    __shared__ float2 buf[4352];
    __shared__ float2 tw[256];               // W4096^t, t = 0..255
    int tid = threadIdx.x;
    int b = blockIdx.x >> 8;
    int d = blockIdx.x & 255;
    {
        float sv, cv;
        sincospif(tid * (1.0f / 2048.0f), &sv, &cv);
        tw[tid] = make_float2(cv, -sv);
    }

    float2 v[16];
    float xreg[16];
    const float* xp = x + (size_t)b * TT * DD + d;
#pragma unroll
    for (int j = 0; j < 16; j++) {
        float val = xp[(size_t)(tid + 256 * j) * DD];
        xreg[j] = val;
        v[j] = make_float2(val, 0.f);
    }
    __syncthreads();                          // tw ready

    // ---- S1 fwd: DFT16 over j (stride 256), twiddle W4096^{t r}, store (r,t)
    dft16<false>(v);
    {
        float2 w = tw[tid];
        buf[SWP(tid)] = v[PRM(0)];
        float2 wk = w;
#pragma unroll
        for (int r = 1; r < 16; r++) {
            buf[SWP(r * 256 + tid)] = cmulf(v[PRM(r)], wk);
            wk = cmulf(wk, w);
        }
    }
    __syncthreads();

    // ---- S2 fwd: per 256-block (fixed r), DFT16 over q, twiddle W256^{p u}
    int blk = tid >> 4, p = tid & 15;
    int B0 = blk * 256;
#pragma unroll
    for (int j = 0; j < 16; j++) v[j] = buf[SWP(B0 + p + 16 * j)];
    dft16<false>(v);
    {
        float2 w = tw[p * 16];                // W256^p
        buf[SWP(B0 + p)] = v[PRM(0)];
        float2 wk = w;
#pragma unroll
        for (int u = 1; u < 16; u++) {
            buf[SWP(B0 + u * 16 + p)] = cmulf(v[PRM(u)], wk);
            wk = cmulf(wk, w);
        }
    }
    __syncthreads();

    // ---- S3 fwd + mask + S3 inv, fully in registers ----
#pragma unroll
    for (int j = 0; j < 16; j++) v[j] = buf[SWP(tid * 16 + j)];
    dft16<false>(v);
    {
        // thread tid = r*16 + u; output freq k = r + 16u + 256w at slot PRM(w)
        const unsigned char* mk = g_mask + b * TT;
        int fbase = (tid & 15) * 16 + (tid >> 4);
#pragma unroll
        for (int m = 0; m < 16; m++)
            if (!mk[m * 256 + fbase]) v[PRM(m)] = make_float2(0.f, 0.f);
        // un-permute in place (PRM is an involution: swap 2-cycles)
#pragma unroll
        for (int m = 0; m < 16; m++) {
            int pm = PRM(m);
            if (m < pm) { float2 t = v[m]; v[m] = v[pm]; v[pm] = t; }
        }
        dft16<true>(v);
#pragma unroll
        for (int t1 = 0; t1 < 16; t1++) buf[SWP(tid * 16 + t1)] = v[PRM(t1)];
    }
    __syncthreads();

    // ---- S2 inv: conj twiddle, then inverse DFT16 back to q positions ----
#pragma unroll
    for (int u = 0; u < 16; u++) v[u] = buf[SWP(B0 + u * 16 + p)];
    {
        float2 w = make_float2(tw[p * 16].x, -tw[p * 16].y);
        float2 wk = w;
#pragma unroll
        for (int u = 1; u < 16; u++) { v[u] = cmulf(v[u], wk); wk = cmulf(wk, w); }
    }
    dft16<true>(v);
#pragma unroll
    for (int q = 0; q < 16; q++) buf[SWP(B0 + p + 16 * q)] = v[PRM(q)];
    __syncthreads();

    // ---- S1 inv + combine, write straight to global ----
#pragma unroll
    for (int r = 0; r < 16; r++) v[r] = buf[SWP(r * 256 + tid)];
    {
        float2 w = make_float2(tw[tid].x, -tw[tid].y);
        float2 wk = w;
#pragma unroll
        for (int r = 1; r < 16; r++) { v[r] = cmulf(v[r], wk); wk = cmulf(wk, w); }
    }
    dft16<true>(v);
    float qf = sf[d & 3];
    float cr = (cosf(qf) - 1.0f) * (1.0f / 4096.0f);
    float ci = sinf(qf) * (1.0f / 4096.0f);
    float* op = out + (size_t)b * TT * DD + d;
#pragma unroll
    for (int n2 = 0; n2 < 16; n2++) {
        float2 uu = v[PRM(n2)];
        op[(size_t)(tid + 256 * n2) * DD] = xreg[n2] + cr * uu.x - ci * uu.y;
    }
}

// ================= launch =================
extern "C" void kernel_launch(void* const* d_in, const int* in_sizes, int n_in,
                              void* d_out, int out_size) {
    const float* x    = (const float*)d_in[0];
    const float* W1   = (const float*)d_in[1];
    const float* b1   = (const float*)d_in[2];
    const float* ln_g = (const float*)d_in[3];
    const float* ln_b = (const float*)d_in[4];
    const float* W2   = (const float*)d_in[5];
    const float* b2   = (const float*)d_in[6];
    const float* tq   = (const float*)d_in[7];
    const float* sf   = (const float*)d_in[8];
    float* out = (float*)d_out;

    cudaFuncSetAttribute(k_encode_mask, cudaFuncAttributeMaxDynamicSharedMemorySize, 81920);

    k_scores<<<BT / 8, 256>>>(x, tq);
    k_softmax<<<BB, 256>>>();
    k_topic_part<<<dim3(16, BB), 256>>>(x);
    k_topic_enc<<<BB, 256>>>(W1, b1, ln_g, ln_b, W2, b2);
    k_encode_mask<<<BT / 64, 256, 81920>>>(x, W1, b1, ln_g, ln_b, W2, b2);
    k_fft_filter<<<BB * DD, 256>>>(x, sf, out);
}

// round 11
// speedup vs baseline: 1.6728x; 1.1443x over previous
#include <cuda_runtime.h>
#include <math.h>

#define BB 32
#define TT 4096
#define DD 256
#define HH 128
#define BT (BB*TT)

// ---- scratch (device globals; no allocation) ----
__device__ float g_scores[BT];           // scores, normalized to weights in place
__device__ float g_part[16*BB*DD];       // main_topic partial sums
__device__ float g_tenc[BB*HH];          // normalized topic encoding
__device__ unsigned char g_mask[BT];     // irrelevance mask per (b, freq)

__device__ __forceinline__ float gelu_exact(float v) {
    return 0.5f * v * (1.0f + erff(v * 0.70710678118654752f));
}

// ---- packed f32x2 helpers (sm_103a FFMA2 path; ptxas never emits this) ----
__device__ __forceinline__ unsigned long long pk2(float lo, float hi) {
    unsigned long long r;
    asm("mov.b64 %0, {%1,%2};" : "=l"(r) : "f"(lo), "f"(hi));
    return r;
}
__device__ __forceinline__ void upk2(unsigned long long v, float& lo, float& hi) {
    asm("mov.b64 {%0,%1}, %2;" : "=f"(lo), "=f"(hi) : "l"(v));
}
#define FMA2(d, a, b, c) asm("fma.rn.f32x2 %0, %1, %2, %3;" : "=l"(d) : "l"(a), "l"(b), "l"(c))

// ================= K1: scores[b,t] = dot(q, x[b,t]) / TEMP =================
__global__ void __launch_bounds__(256) k_scores(const float* __restrict__ x,
                                                const float* __restrict__ tq) {
    int warp = (blockIdx.x * blockDim.x + threadIdx.x) >> 5;
    int lane = threadIdx.x & 31;
    if (warp >= BT) return;
    const float* xr = x + (size_t)warp * DD;
    float s = 0.f;
#pragma unroll
    for (int i = 0; i < 8; i++) {
        int c = lane + 32 * i;
        s += xr[c] * __ldg(tq + c);
    }
#pragma unroll
    for (int o = 16; o; o >>= 1) s += __shfl_xor_sync(0xffffffffu, s, o);
    if (lane == 0) g_scores[warp] = s * 2.0f;   // 1/TEMPERATURE = 2
}

// ================= K2: per-b softmax over T, in place =================
__global__ void __launch_bounds__(256) k_softmax() {
    int b = blockIdx.x;
    int tid = threadIdx.x;
    __shared__ float red[256];
    float* s = g_scores + b * TT;
    float v[16];
    float mx = -1e30f;
#pragma unroll
    for (int i = 0; i < 16; i++) { v[i] = s[tid + 256 * i]; mx = fmaxf(mx, v[i]); }
    red[tid] = mx; __syncthreads();
    for (int o = 128; o; o >>= 1) { if (tid < o) red[tid] = fmaxf(red[tid], red[tid + o]); __syncthreads(); }
    mx = red[0]; __syncthreads();
    float sum = 0.f;
#pragma unroll
    for (int i = 0; i < 16; i++) { v[i] = expf(v[i] - mx); sum += v[i]; }
    red[tid] = sum; __syncthreads();
    for (int o = 128; o; o >>= 1) { if (tid < o) red[tid] += red[tid + o]; __syncthreads(); }
    float inv = 1.0f / red[0];
#pragma unroll
    for (int i = 0; i < 16; i++) s[tid + 256 * i] = v[i] * inv;
}

// ================= K3: main_topic partials over t-chunks =================
__global__ void __launch_bounds__(256) k_topic_part(const float* __restrict__ x) {
    int chunk = blockIdx.x;          // 0..15
    int b = blockIdx.y;              // 0..31
    int d = threadIdx.x;             // 0..255
    __shared__ float w[256];
    int t0 = chunk * 256;
    w[d] = g_scores[b * TT + t0 + d];
    __syncthreads();
    float acc = 0.f;
    const float* xp = x + ((size_t)b * TT + t0) * DD + d;
#pragma unroll 4
    for (int t = 0; t < 256; t++) acc += w[t] * xp[(size_t)t * DD];
    g_part[(chunk * BB + b) * DD + d] = acc;
}

// ================= K4: encode main_topic, normalize =================
__global__ void __launch_bounds__(256) k_topic_enc(
    const float* __restrict__ W1, const float* __restrict__ b1,
    const float* __restrict__ lng, const float* __restrict__ lnb,
    const float* __restrict__ W2, const float* __restrict__ b2) {
    int b = blockIdx.x, tid = threadIdx.x;
    __shared__ float mt[256], red[256], red2[256], gbuf[256];
    float acc = 0.f;
#pragma unroll
    for (int c = 0; c < 16; c++) acc += g_part[(c * BB + b) * DD + tid];
    mt[tid] = acc;
    __syncthreads();
    float h = b1[tid];
    for (int k = 0; k < DD; k++) h += mt[k] * W1[k * DD + tid];
    red[tid] = h; red2[tid] = h * h;
    __syncthreads();
    for (int o = 128; o; o >>= 1) {
        if (tid < o) { red[tid] += red[tid + o]; red2[tid] += red2[tid + o]; }
        __syncthreads();
    }
    float mu = red[0] * (1.f / 256.f);
    float var = red2[0] * (1.f / 256.f) - mu * mu;
    float n = (h - mu) * rsqrtf(var + 1e-5f) * lng[tid] + lnb[tid];
    float g = gelu_exact(n);
    __syncthreads();
    gbuf[tid] = g;
    __syncthreads();
    float e = 0.f;
    if (tid < HH) {
        e = b2[tid];
        for (int k = 0; k < DD; k++) e += gbuf[k] * W2[k * HH + tid];
    }
    red[tid] = (tid < HH) ? e * e : 0.f;
    __syncthreads();
    for (int o = 128; o; o >>= 1) { if (tid < o) red[tid] += red[tid + o]; __syncthreads(); }
    if (tid < HH) {
        float nrm = fmaxf(sqrtf(red[0]), 1e-12f);
        g_tenc[b * HH + tid] = e / nrm;
    }
}

// ================= K5: encoder GEMMs (fma.rn.f32x2) + LN + GELU + mask =======
__global__ void __launch_bounds__(256) k_encode_mask(
    const float* __restrict__ x, const float* __restrict__ W1,
    const float* __restrict__ b1, const float* __restrict__ lng,
    const float* __restrict__ lnb, const float* __restrict__ W2,
    const float* __restrict__ b2) {
    extern __shared__ float sm[];
    float* As = sm;                  // [16][65]  (phase A)
    float* Bs = sm + 16 * 65;        // [16][256] (phase A)
    float* G   = sm;                 // [64][256] (phase B, aliases)
    float* W2s = sm + 64 * 256;      // [32][128] (phase B)

    int tid = threadIdx.x;
    int tx = tid & 31, ty = tid >> 5;        // 32 x 8
    int row0 = blockIdx.x * 64;
    int b = row0 >> 12;                       // T = 4096

    unsigned long long acc[8][4];
#pragma unroll
    for (int i = 0; i < 8; i++)
#pragma unroll
        for (int j = 0; j < 4; j++) acc[i][j] = 0ULL;

    for (int kb = 0; kb < 16; kb++) {
        int k0 = kb * 16;
        __syncthreads();
#pragma unroll
        for (int it = 0; it < 4; it++) {
            int lin = it * 256 + tid;
            int r = lin >> 4, kk = lin & 15;
            As[kk * 65 + r] = x[((size_t)(row0 + r)) * DD + k0 + kk];
        }
#pragma unroll
        for (int it = 0; it < 16; it++)
            Bs[it * 256 + tid] = W1[(size_t)(k0 + it) * DD + tid];
        __syncthreads();
#pragma unroll
        for (int kk = 0; kk < 16; kk++) {
            unsigned long long A2[8], bb[4];
#pragma unroll
            for (int i = 0; i < 8; i++) {
                float a = As[kk * 65 + ty * 8 + i];
                A2[i] = pk2(a, a);
            }
#pragma unroll
            for (int j = 0; j < 4; j++)
                bb[j] = *(const unsigned long long*)&Bs[kk * 256 + 2 * tx + 64 * j];
#pragma unroll
            for (int i = 0; i < 8; i++)
#pragma unroll
                for (int j = 0; j < 4; j++)
                    FMA2(acc[i][j], A2[i], bb[j], acc[i][j]);
        }
    }

    // epilogue 1: +b1, LayerNorm per row (warp owns 8 rows), GELU -> G smem
    float bv[8], gv[8], btv[8];
#pragma unroll
    for (int j = 0; j < 4; j++) {
        int c = 2 * tx + 64 * j;
        float2 t;
        t = *(const float2*)(b1 + c);  bv[2 * j] = t.x;  bv[2 * j + 1] = t.y;
        t = *(const float2*)(lng + c); gv[2 * j] = t.x;  gv[2 * j + 1] = t.y;
        t = *(const float2*)(lnb + c); btv[2 * j] = t.x; btv[2 * j + 1] = t.y;
    }
    __syncthreads();   // done with As/Bs before overwriting with G
#pragma unroll
    for (int i = 0; i < 8; i++) {
        float h[8];
#pragma unroll
        for (int j = 0; j < 4; j++) {
            float lo, hi; upk2(acc[i][j], lo, hi);
            h[2 * j] = lo + bv[2 * j];
            h[2 * j + 1] = hi + bv[2 * j + 1];
        }
        float s = 0.f, s2 = 0.f;
#pragma unroll
        for (int j = 0; j < 8; j++) { s += h[j]; s2 += h[j] * h[j]; }
#pragma unroll
        for (int o = 16; o; o >>= 1) {
            s  += __shfl_xor_sync(0xffffffffu, s, o);
            s2 += __shfl_xor_sync(0xffffffffu, s2, o);
        }
        float mu = s * (1.f / 256.f);
        float var = s2 * (1.f / 256.f) - mu * mu;
        float rstd = rsqrtf(var + 1e-5f);
        int r = ty * 8 + i;
#pragma unroll
        for (int j = 0; j < 4; j++) {
            float g0 = gelu_exact((h[2 * j] - mu) * rstd * gv[2 * j] + btv[2 * j]);
            float g1 = gelu_exact((h[2 * j + 1] - mu) * rstd * gv[2 * j + 1] + btv[2 * j + 1]);
            *(float2*)&G[r * 256 + 2 * tx + 64 * j] = make_float2(g0, g1);
        }
    }
    __syncthreads();

    // phase B: GEMM2 [64,256] x [256,128]
    unsigned long long acc2[8][2];
#pragma unroll
    for (int i = 0; i < 8; i++) { acc2[i][0] = 0ULL; acc2[i][1] = 0ULL; }
    for (int kb = 0; kb < 8; kb++) {
#pragma unroll
        for (int it = 0; it < 16; it++) {
            int lin = it * 256 + tid;
            int kk = lin >> 7, c = lin & 127;
            W2s[kk * 128 + c] = W2[(size_t)(kb * 32 + kk) * HH + c];
        }
        __syncthreads();
#pragma unroll
        for (int kk = 0; kk < 32; kk++) {
            unsigned long long A2[8], bb[2];
#pragma unroll
            for (int i = 0; i < 8; i++) {
                float a = G[(ty * 8 + i) * 256 + kb * 32 + kk];
                A2[i] = pk2(a, a);
            }
            bb[0] = *(const unsigned long long*)&W2s[kk * 128 + 2 * tx];
            bb[1] = *(const unsigned long long*)&W2s[kk * 128 + 2 * tx + 64];
#pragma unroll
            for (int i = 0; i < 8; i++) {
                FMA2(acc2[i][0], A2[i], bb[0], acc2[i][0]);
                FMA2(acc2[i][1], A2[i], bb[1], acc2[i][1]);
            }
        }
        __syncthreads();
    }

    // epilogue 2: +b2, cosine relevance vs normalized topic encoding, mask
    float tqv[4], b2v[4];
#pragma unroll
    for (int j = 0; j < 2; j++) {
        int c = 2 * tx + 64 * j;
        float2 t;
        t = *(const float2*)(&g_tenc[b * HH + c]); tqv[2 * j] = t.x; tqv[2 * j + 1] = t.y;
        t = *(const float2*)(b2 + c);              b2v[2 * j] = t.x; b2v[2 * j + 1] = t.y;
    }
#pragma unroll
    for (int i = 0; i < 8; i++) {
        float e[4];
        { float lo, hi; upk2(acc2[i][0], lo, hi); e[0] = lo + b2v[0]; e[1] = hi + b2v[1]; }
        { float lo, hi; upk2(acc2[i][1], lo, hi); e[2] = lo + b2v[2]; e[3] = hi + b2v[3]; }
        float ss = 0.f, dt = 0.f;
#pragma unroll
        for (int j = 0; j < 4; j++) { ss += e[j] * e[j]; dt += e[j] * tqv[j]; }
#pragma unroll
        for (int o = 16; o; o >>= 1) {
            ss += __shfl_xor_sync(0xffffffffu, ss, o);
            dt += __shfl_xor_sync(0xffffffffu, dt, o);
        }
        float rel = dt / fmaxf(sqrtf(ss), 1e-12f);
        if (tx == i) g_mask[row0 + ty * 8 + i] = (rel < 0.4f) ? 1 : 0;
    }
}

// ================= K6: radix-16 fused FFT, 4 channels per CTA ===============
// 4096 = 16^3. Same math as R8; data movement changed: CTA owns channels
// d0..d0+3 (float4 global access, 2x sector amp instead of 8x). One 34KB
// work plane reused per channel; results parked in 4 real planes; final
// gather writes coalesced float4.
__device__ __forceinline__ float2 cmulf(float2 a, float2 b) {
    return make_float2(a.x * b.x - a.y * b.y, a.x * b.y + a.y * b.x);
}

// 16-pt DFT, input natural order a[j], output index m lands in slot PRM(m).
template<bool INV>
__device__ __forceinline__ void dft16(float2* a) {
#pragma unroll
    for (int j0 = 0; j0 < 4; j0++) {                 // radix-4 over j = j0 + 4*jq
        float2 A0 = a[j0], A1 = a[j0 + 4], A2 = a[j0 + 8], A3 = a[j0 + 12];
        float s02r = A0.x + A2.x, s02i = A0.y + A2.y;
        float d02r = A0.x - A2.x, d02i = A0.y - A2.y;
        float s13r = A1.x + A3.x, s13i = A1.y + A3.y;
        float d13r = A1.x - A3.x, d13i = A1.y - A3.y;
        a[j0]     = make_float2(s02r + s13r, s02i + s13i);
        a[j0 + 8] = make_float2(s02r - s13r, s02i - s13i);
        if (!INV) {
            a[j0 + 4]  = make_float2(d02r + d13i, d02i - d13r);
            a[j0 + 12] = make_float2(d02r - d13i, d02i + d13r);
        } else {
            a[j0 + 4]  = make_float2(d02r - d13i, d02i + d13r);
            a[j0 + 12] = make_float2(d02r + d13i, d02i - d13r);
        }
    }
    const float C1 = 0.9238795325112867f, S1 = 0.3826834323650898f, R2 = 0.7071067811865476f;
    const float SG = INV ? 1.f : -1.f;
    a[5]  = cmulf(a[5],  make_float2( C1,  SG * S1));
    a[6]  = cmulf(a[6],  make_float2( R2,  SG * R2));
    a[7]  = cmulf(a[7],  make_float2( S1,  SG * C1));
    a[9]  = cmulf(a[9],  make_float2( R2,  SG * R2));
    a[10] = cmulf(a[10], make_float2( 0.f, SG * 1.f));
    a[11] = cmulf(a[11], make_float2(-R2,  SG * R2));
    a[13] = cmulf(a[13], make_float2( S1,  SG * C1));
    a[14] = cmulf(a[14], make_float2(-R2,  SG * R2));
    a[15] = cmulf(a[15], make_float2(-C1, -SG * S1));
#pragma unroll
    for (int r0 = 0; r0 < 4; r0++) {                 // radix-4 within groups of 4
        float2 A0 = a[4 * r0], A1 = a[4 * r0 + 1], A2 = a[4 * r0 + 2], A3 = a[4 * r0 + 3];
        float s02r = A0.x + A2.x, s02i = A0.y + A2.y;
        float d02r = A0.x - A2.x, d02i = A0.y - A2.y;
        float s13r = A1.x + A3.x, s13i = A1.y + A3.y;
        float d13r = A1.x - A3.x, d13i = A1.y - A3.y;
        a[4 * r0]     = make_float2(s02r + s13r, s02i + s13i);
        a[4 * r0 + 2] = make_float2(s02r - s13r, s02i - s13i);
        if (!INV) {
            a[4 * r0 + 1] = make_float2(d02r + d13i, d02i - d13r);
            a[4 * r0 + 3] = make_float2(d02r - d13i, d02i + d13r);
        } else {
            a[4 * r0 + 1] = make_float2(d02r - d13i, d02i + d13r);
            a[4 * r0 + 3] = make_float2(d02r + d13i, d02i - d13r);
        }
    }
}
#define PRM(m) (4 * ((m) & 3) + ((m) >> 2))   // involution: base-4 digit swap
#define SWP(i) ((i) + ((i) >> 4))             // pad 1 float2 per 16

__global__ void __launch_bounds__(256) k_fft_filter(
    const float* __restrict__ x, const float* __restrict__ sf,
    float* __restrict__ out) {
    extern __shared__ float2 dynsm[];
    float2* tw  = dynsm;                        // 256 float2 : W4096^t
    float2* buf = dynsm + 256;                  // 4352 float2: work plane
    float* res  = (float*)(dynsm + 256 + 4352); // 4 * 4096 floats

    int tid = threadIdx.x;
    int b = blockIdx.x >> 6;
    int d0 = (blockIdx.x & 63) * 4;
    {
        float sv, cv;
        sincospif(tid * (1.0f / 2048.0f), &sv, &cv);
        tw[tid] = make_float2(cv, -sv);
    }

    // coalesced-ish float4 loads: 4 channels of x kept in registers
    float xreg[64];
    const float* xp = x + (size_t)b * TT * DD + d0;
#pragma unroll
    for (int j = 0; j < 16; j++) {
        float4 q4 = *(const float4*)(xp + (size_t)(tid + 256 * j) * DD);
        xreg[j]      = q4.x;
        xreg[16 + j] = q4.y;
        xreg[32 + j] = q4.z;
        xreg[48 + j] = q4.w;
    }

    // mask bitmask (identical for all 4 channels)
    int blk = tid >> 4, p = tid & 15;
    int B0 = blk * 256;
    const unsigned char* mk = g_mask + b * TT;
    int fbase = p * 16 + blk;
    unsigned m16 = 0;
#pragma unroll
    for (int m = 0; m < 16; m++)
        if (mk[m * 256 + fbase]) m16 |= (1u << m);

    __syncthreads();                          // tw ready

    for (int c = 0; c < 4; c++) {
        float2 v[16];
#pragma unroll
        for (int j = 0; j < 16; j++) v[j] = make_float2(xreg[c * 16 + j], 0.f);

        // ---- S1 fwd: DFT16 over j (stride 256), twiddle W4096^{t r} ----
        dft16<false>(v);
        {
            float2 w = tw[tid];
            buf[SWP(tid)] = v[PRM(0)];
            float2 wk = w;
#pragma unroll
            for (int r = 1; r < 16; r++) {
                buf[SWP(r * 256 + tid)] = cmulf(v[PRM(r)], wk);
                wk = cmulf(wk, w);
            }
        }
        __syncthreads();

        // ---- S2 fwd: per 256-block (fixed r), DFT16 over q, tw W256^{p u} ----
#pragma unroll
        for (int j = 0; j < 16; j++) v[j] = buf[SWP(B0 + p + 16 * j)];
        dft16<false>(v);
        {
            float2 w = tw[p * 16];            // W256^p
            buf[SWP(B0 + p)] = v[PRM(0)];
            float2 wk = w;
#pragma unroll
            for (int u = 1; u < 16; u++) {
                buf[SWP(B0 + u * 16 + p)] = cmulf(v[PRM(u)], wk);
                wk = cmulf(wk, w);
            }
        }
        __syncthreads();

        // ---- S3 fwd + mask + S3 inv, fully in registers ----
#pragma unroll
        for (int j = 0; j < 16; j++) v[j] = buf[SWP(tid * 16 + j)];
        dft16<false>(v);
        {
#pragma unroll
            for (int m = 0; m < 16; m++)
                if (!((m16 >> m) & 1)) v[PRM(m)] = make_float2(0.f, 0.f);
#pragma unroll
            for (int m = 0; m < 16; m++) {
                int pm = PRM(m);
                if (m < pm) { float2 t = v[m]; v[m] = v[pm]; v[pm] = t; }
            }
            dft16<true>(v);
#pragma unroll
            for (int t1 = 0; t1 < 16; t1++) buf[SWP(tid * 16 + t1)] = v[PRM(t1)];
        }
        __syncthreads();

        // ---- S2 inv: conj twiddle, then inverse DFT16 ----
#pragma unroll
        for (int u = 0; u < 16; u++) v[u] = buf[SWP(B0 + u * 16 + p)];
        {
            float2 w = make_float2(tw[p * 16].x, -tw[p * 16].y);
            float2 wk = w;
#pragma unroll
            for (int u = 1; u < 16; u++) { v[u] = cmulf(v[u], wk); wk = cmulf(wk, w); }
        }
        dft16<true>(v);
#pragma unroll
        for (int q = 0; q < 16; q++) buf[SWP(B0 + p + 16 * q)] = v[PRM(q)];
        __syncthreads();

        // ---- S1 inv + combine into result plane ----
#pragma unroll
        for (int r = 0; r < 16; r++) v[r] = buf[SWP(r * 256 + tid)];
        {
            float2 w = make_float2(tw[tid].x, -tw[tid].y);
            float2 wk = w;
#pragma unroll
            for (int r = 1; r < 16; r++) { v[r] = cmulf(v[r], wk); wk = cmulf(wk, w); }
        }
        dft16<true>(v);
        float qf = __ldg(sf + c);             // d0 % 4 == 0 -> (d0+c)&3 == c
        float cr = (cosf(qf) - 1.0f) * (1.0f / 4096.0f);
        float ci = sinf(qf) * (1.0f / 4096.0f);
        float* rp = res + c * 4096;
#pragma unroll
        for (int n2 = 0; n2 < 16; n2++) {
            float2 uu = v[PRM(n2)];
            rp[tid + 256 * n2] = xreg[c * 16 + n2] + cr * uu.x - ci * uu.y;
        }
        __syncthreads();   // res写 done + work plane free for next channel
    }

    // ---- final gather: coalesced float4 stores ----
    float* op = out + (size_t)b * TT * DD + d0;
#pragma unroll
    for (int j = 0; j < 16; j++) {
        int t = tid + 256 * j;
        float4 o4 = make_float4(res[t], res[4096 + t], res[8192 + t], res[12288 + t]);
        *(float4*)(op + (size_t)t * DD) = o4;
    }
}

// ================= launch =================
extern "C" void kernel_launch(void* const* d_in, const int* in_sizes, int n_in,
                              void* d_out, int out_size) {
    const float* x    = (const float*)d_in[0];
    const float* W1   = (const float*)d_in[1];
    const float* b1   = (const float*)d_in[2];
    const float* ln_g = (const float*)d_in[3];
    const float* ln_b = (const float*)d_in[4];
    const float* W2   = (const float*)d_in[5];
    const float* b2   = (const float*)d_in[6];
    const float* tq   = (const float*)d_in[7];
    const float* sf   = (const float*)d_in[8];
    float* out = (float*)d_out;

    const int fft_smem = (256 + 4352) * (int)sizeof(float2) + 4 * 4096 * (int)sizeof(float);
    cudaFuncSetAttribute(k_encode_mask, cudaFuncAttributeMaxDynamicSharedMemorySize, 81920);
    cudaFuncSetAttribute(k_fft_filter, cudaFuncAttributeMaxDynamicSharedMemorySize, fft_smem);

    k_scores<<<BT / 8, 256>>>(x, tq);
    k_softmax<<<BB, 256>>>();
    k_topic_part<<<dim3(16, BB), 256>>>(x);
    k_topic_enc<<<BB, 256>>>(W1, b1, ln_g, ln_b, W2, b2);
    k_encode_mask<<<BT / 64, 256, 81920>>>(x, W1, b1, ln_g, ln_b, W2, b2);
    k_fft_filter<<<BB * (DD / 4), 256, fft_smem>>>(x, sf, out);
}